// round 7
// baseline (speedup 1.0000x reference)
#include <cuda_runtime.h>
#include <cuda_bf16.h>
#include <cstdint>

#define BB 4
#define C 256
#define H 64
#define W 64
#define HW 4096
#define G 32
#define KK 9
#define OC_OFF 18
#define CK 2304  /* C * KK */

// ---------------- device scratch (static, no runtime allocation) -------------
__device__ float g_offset[BB * OC_OFF * HW];                             // 1.18 MB
__device__ __align__(16) unsigned short g_val_hi[(size_t)BB * HW * CK];  // 75.5 MB
__device__ __align__(16) unsigned short g_val_lo[(size_t)BB * HW * CK];  // 75.5 MB
__device__ __align__(16) unsigned short g_whi[2 * C * CK];               // 2.36 MB
__device__ __align__(16) unsigned short g_wlo[2 * C * CK];               // 2.36 MB
__device__ float g_tmp[(size_t)BB * C * HW];                             // 16.8 MB
__device__ float g_act[(size_t)BB * C * HW];                             // 16.8 MB
__device__ float g_stat[BB * G * 2];                                     // group sums

// ---------------- helpers ----------------------------------------------------
__device__ __forceinline__ uint32_t smem_u32(const void* p) {
    uint32_t a;
    asm("{ .reg .u64 t; cvta.to.shared.u64 t, %1; cvt.u32.u64 %0, t; }"
        : "=r"(a) : "l"(p));
    return a;
}
__device__ __forceinline__ void cp16(uint32_t saddr, const void* gaddr) {
    asm volatile("cp.async.cg.shared.global [%0], [%1], 16;"
                 :: "r"(saddr), "l"(gaddr));
}

#define MMA_BF16(d, a, bfr)                                                  \
    asm volatile(                                                            \
        "mma.sync.aligned.m16n8k16.row.col.f32.bf16.bf16.f32 "               \
        "{%0,%1,%2,%3}, {%4,%5,%6,%7}, {%8,%9}, {%0,%1,%2,%3};"              \
        : "+f"((d)[0]), "+f"((d)[1]), "+f"((d)[2]), "+f"((d)[3])             \
        : "r"((a)[0]), "r"((a)[1]), "r"((a)[2]), "r"((a)[3]),                \
          "r"((bfr)[0]), "r"((bfr)[1]))

#define LDSM_X4(fr, addr)                                                    \
    asm volatile("ldmatrix.sync.aligned.m8n8.x4.shared.b16 "                 \
                 "{%0,%1,%2,%3}, [%4];"                                      \
                 : "=r"((fr)[0]), "=r"((fr)[1]), "=r"((fr)[2]), "=r"((fr)[3])\
                 : "r"(addr))

#define LDSM_X2(fr, addr)                                                    \
    asm volatile("ldmatrix.sync.aligned.m8n8.x2.shared.b16 {%0,%1}, [%2];"   \
                 : "=r"((fr)[0]), "=r"((fr)[1]) : "r"(addr))

// ---------------- init offset buffer with bias + clear group stats -----------
__global__ void init_offset_kernel(const float* __restrict__ bias) {
    int i = blockIdx.x * 256 + threadIdx.x;
    if (blockIdx.x == 0 && threadIdx.x < BB * G * 2) g_stat[threadIdx.x] = 0.f;
    if (i < BB * OC_OFF * HW) {
        int oc = (i / HW) % OC_OFF;
        g_offset[i] = bias[oc];
    }
}

// ---------------- weight split/reorder: w[oc][cin][k] -> [oc][k*256+cin] -----
__global__ void wprep_kernel(const float* __restrict__ w1, const float* __restrict__ w2) {
    int i = blockIdx.x * 256 + threadIdx.x;
    if (i >= 2 * C * CK) return;
    int s = i / (C * CK);
    int rem = i - s * (C * CK);
    int oc = rem / CK;
    int r = rem - oc * CK;
    int k = r >> 8;
    int cin = r & 255;
    const float* w = s ? w2 : w1;
    float v = w[(size_t)oc * CK + cin * 9 + k];
    __nv_bfloat16 h = __float2bfloat16(v);
    g_whi[i] = __bfloat16_as_ushort(h);
    g_wlo[i] = __bfloat16_as_ushort(__float2bfloat16(v - __bfloat162float(h)));
}

// ---------------- offset conv3x3: C in -> 18 out, pad 1 ----------------------
#define CIN_CHUNK 64
__global__ __launch_bounds__(256) void offset_conv_kernel(
    const float* __restrict__ xin, const float* __restrict__ woff, int use_internal) {
    __shared__ __align__(16) float ws[CIN_CHUNK * 9 * 20];
    __shared__ float xs[18 * 18];

    int tid = threadIdx.x;
    int bz = blockIdx.z;
    int b = bz >> 2;
    int chunk = bz & 3;
    int cin0 = chunk * CIN_CHUNK;

    for (int idx = tid; idx < CIN_CHUNK * 9 * 18; idx += 256) {
        int cl = idx / 162;
        int rem = idx - cl * 162;
        int k = rem / 18;
        int oc = rem - k * 18;
        ws[(cl * 9 + k) * 20 + oc] =
            woff[(size_t)oc * (C * 9) + (size_t)(cin0 + cl) * 9 + k];
    }

    int ty = tid >> 4, tx = tid & 15;
    int py0 = blockIdx.y * 16, px0 = blockIdx.x * 16;

    float acc[18];
#pragma unroll
    for (int i = 0; i < 18; i++) acc[i] = 0.f;

    const float* src = use_internal ? g_act : xin;
    const float* xb = src + ((size_t)b * C + cin0) * HW;

    __syncthreads();

    for (int cl = 0; cl < CIN_CHUNK; cl++) {
        const float* xc = xb + (size_t)cl * HW;
        for (int idx = tid; idx < 324; idx += 256) {
            int r = idx / 18, cc = idx - r * 18;
            int gy = py0 - 1 + r, gx = px0 - 1 + cc;
            float v = 0.f;
            if (gy >= 0 && gy < H && gx >= 0 && gx < W) v = xc[gy * W + gx];
            xs[idx] = v;
        }
        __syncthreads();

        float xv[9];
#pragma unroll
        for (int ky = 0; ky < 3; ky++)
#pragma unroll
            for (int kx = 0; kx < 3; kx++)
                xv[ky * 3 + kx] = xs[(ty + ky) * 18 + (tx + kx)];

#pragma unroll
        for (int k = 0; k < 9; k++) {
            const float* wr = &ws[(cl * 9 + k) * 20];
            float xk = xv[k];
#pragma unroll
            for (int oc = 0; oc < 18; oc++) acc[oc] += xk * wr[oc];
        }
        __syncthreads();
    }

    int p = (py0 + ty) * W + (px0 + tx);
    float* ob = g_offset + (size_t)b * OC_OFF * HW + p;
#pragma unroll
    for (int oc = 0; oc < 18; oc++) atomicAdd(ob + (size_t)oc * HW, acc[oc]);
}

// ---------------- bilinear gather -> val_{hi,lo}[b][p][k*256+cin] ------------
// grid (16, 9, B*4): z = b*4 + channel chunk of 64. One thread per pixel.
__global__ __launch_bounds__(256) void gather_kernel(const float* __restrict__ xin,
                                                     int use_internal) {
    int tid = threadIdx.x;
    int p = blockIdx.x * 256 + tid;
    int k = blockIdx.y;
    int b = blockIdx.z >> 2;
    int cin0 = (blockIdx.z & 3) * 64;
    int h = p >> 6, w = p & 63;

    const float* off = g_offset + ((size_t)b * OC_OFF + 2 * k) * HW + p;
    float dy = off[0];
    float dx = off[HW];
    int ky = k / 3, kx = k - ky * 3;

    float py = dy + (float)(h - 1 + ky);
    float px = dx + (float)(w - 1 + kx);
    float fy = floorf(py), fx = floorf(px);
    int iy0 = (int)fy, ix0 = (int)fx;
    float ly = py - fy, lx = px - fx;

    float vy0 = (iy0 >= 0 && iy0 < H) ? 1.f : 0.f;
    float vy1 = (iy0 + 1 >= 0 && iy0 + 1 < H) ? 1.f : 0.f;
    float vx0 = (ix0 >= 0 && ix0 < W) ? 1.f : 0.f;
    float vx1 = (ix0 + 1 >= 0 && ix0 + 1 < W) ? 1.f : 0.f;

    float w00 = (1.f - ly) * (1.f - lx) * vy0 * vx0;
    float w01 = (1.f - ly) * lx * vy0 * vx1;
    float w10 = ly * (1.f - lx) * vy1 * vx0;
    float w11 = ly * lx * vy1 * vx1;

    int cy0 = min(max(iy0, 0), H - 1);
    int cy1 = min(max(iy0 + 1, 0), H - 1);
    int cx0 = min(max(ix0, 0), W - 1);
    int cx1 = min(max(ix0 + 1, 0), W - 1);
    int i00 = cy0 * W + cx0, i01 = cy0 * W + cx1;
    int i10 = cy1 * W + cx0, i11 = cy1 * W + cx1;

    const float* src = use_internal ? g_act : xin;
    const float* xb = src + (size_t)b * C * HW;
    size_t vbase = ((size_t)b * HW + p) * CK + (size_t)k * 256;
    unsigned short* vh = g_val_hi + vbase;
    unsigned short* vl = g_val_lo + vbase;

    for (int c0 = cin0; c0 < cin0 + 64; c0 += 8) {
        __align__(16) unsigned short hb[8];
        __align__(16) unsigned short lb[8];
#pragma unroll
        for (int j = 0; j < 8; j++) {
            const float* xc = xb + (size_t)(c0 + j) * HW;
            float s = w00 * __ldg(xc + i00) + w01 * __ldg(xc + i01) +
                      w10 * __ldg(xc + i10) + w11 * __ldg(xc + i11);
            __nv_bfloat16 hv = __float2bfloat16(s);
            hb[j] = __bfloat16_as_ushort(hv);
            lb[j] = __bfloat16_as_ushort(__float2bfloat16(s - __bfloat162float(hv)));
        }
        *reinterpret_cast<uint4*>(vh + c0) = *reinterpret_cast<const uint4*>(hb);
        *reinterpret_cast<uint4*>(vl + c0) = *reinterpret_cast<const uint4*>(lb);
    }
}

// ---------------- HMMA GEMM: D[p, oc] = sum_r val[p][r] * W[oc][r] -----------
// CTA tile 128(pixels) x 128(oc), KC=32 double-buffered cp.async.
// bf16x3 split: AhBh + AlBh + AhBl, fp32 accum. 8 warps, 64x32 warp tiles.
// Epilogue also accumulates per-group sum / sum^2 into g_stat for fused GN.
#define KC 32
#define NKC (CK / KC) /* 72 */
#define ROWB 80
#define A_HI 0
#define A_LO (128 * ROWB)
#define B_HI (2 * 128 * ROWB)
#define B_LO (3 * 128 * ROWB)
#define BUFSZ (4 * 128 * ROWB) /* 40960 */
#define GSMEM (2 * BUFSZ)      /* 81920 */

__global__ __launch_bounds__(256, 2) void mma_gemm_kernel(int stage) {
    extern __shared__ __align__(16) char smem[];
    uint32_t sb = smem_u32(smem);
    int tid = threadIdx.x;
    int wid = tid >> 5, lane = tid & 31;
    int b = blockIdx.z;
    int n0 = blockIdx.y * 128;
    int p0 = blockIdx.x * 128;

    const unsigned short* Ah = g_val_hi + ((size_t)b * HW + p0) * CK;
    const unsigned short* Al = g_val_lo + ((size_t)b * HW + p0) * CK;
    const unsigned short* Bh = g_whi + ((size_t)stage * C + n0) * CK;
    const unsigned short* Bl = g_wlo + ((size_t)stage * C + n0) * CK;

    int lrow = tid >> 1;
    int lseg = (tid & 1) * 2;
    size_t goff = (size_t)lrow * CK + lseg * 8;
    uint32_t soff = (uint32_t)lrow * ROWB + (uint32_t)lseg * 16;

    int mwarp = wid >> 2, nwarp = wid & 3;
    uint32_t aoff = (uint32_t)(mwarp * 64 + (lane & 15)) * ROWB + (lane >> 4) * 16;
    uint32_t boff = (uint32_t)(nwarp * 32 + (lane & 7)) * ROWB + ((lane >> 3) & 1) * 16;

    float acc[4][4][4];
#pragma unroll
    for (int i = 0; i < 4; i++)
#pragma unroll
        for (int j = 0; j < 4; j++)
#pragma unroll
            for (int q = 0; q < 4; q++) acc[i][j][q] = 0.f;

    {
        uint32_t bufb = sb;
        cp16(bufb + A_HI + soff, Ah + goff);
        cp16(bufb + A_HI + soff + 16, Ah + goff + 8);
        cp16(bufb + A_LO + soff, Al + goff);
        cp16(bufb + A_LO + soff + 16, Al + goff + 8);
        cp16(bufb + B_HI + soff, Bh + goff);
        cp16(bufb + B_HI + soff + 16, Bh + goff + 8);
        cp16(bufb + B_LO + soff, Bl + goff);
        cp16(bufb + B_LO + soff + 16, Bl + goff + 8);
        asm volatile("cp.async.commit_group;" ::: "memory");
    }

#pragma unroll 1
    for (int i = 0; i < NKC; i++) {
        if (i + 1 < NKC) {
            uint32_t bufb = sb + (uint32_t)((i + 1) & 1) * BUFSZ;
            int kc = (i + 1) * KC;
            cp16(bufb + A_HI + soff, Ah + goff + kc);
            cp16(bufb + A_HI + soff + 16, Ah + goff + kc + 8);
            cp16(bufb + A_LO + soff, Al + goff + kc);
            cp16(bufb + A_LO + soff + 16, Al + goff + kc + 8);
            cp16(bufb + B_HI + soff, Bh + goff + kc);
            cp16(bufb + B_HI + soff + 16, Bh + goff + kc + 8);
            cp16(bufb + B_LO + soff, Bl + goff + kc);
            cp16(bufb + B_LO + soff + 16, Bl + goff + kc + 8);
            asm volatile("cp.async.commit_group;" ::: "memory");
            asm volatile("cp.async.wait_group 1;" ::: "memory");
        } else {
            asm volatile("cp.async.wait_group 0;" ::: "memory");
        }
        __syncthreads();

        uint32_t cb = sb + (uint32_t)(i & 1) * BUFSZ;
#pragma unroll
        for (int kk = 0; kk < 2; kk++) {
            uint32_t koff = (uint32_t)kk * 32;
            uint32_t ah[4][4], bhf[4][2];
#pragma unroll
            for (int nt = 0; nt < 4; nt++)
                LDSM_X2(bhf[nt], cb + B_HI + boff + (uint32_t)(nt * 8) * ROWB + koff);
#pragma unroll
            for (int mt = 0; mt < 4; mt++)
                LDSM_X4(ah[mt], cb + A_HI + aoff + (uint32_t)(mt * 16) * ROWB + koff);
#pragma unroll
            for (int mt = 0; mt < 4; mt++)
#pragma unroll
                for (int nt = 0; nt < 4; nt++) MMA_BF16(acc[mt][nt], ah[mt], bhf[nt]);
#pragma unroll
            for (int mt = 0; mt < 4; mt++) {
                uint32_t alf[4];
                LDSM_X4(alf, cb + A_LO + aoff + (uint32_t)(mt * 16) * ROWB + koff);
#pragma unroll
                for (int nt = 0; nt < 4; nt++) MMA_BF16(acc[mt][nt], alf, bhf[nt]);
            }
#pragma unroll
            for (int nt = 0; nt < 4; nt++) {
                uint32_t blf[2];
                LDSM_X2(blf, cb + B_LO + boff + (uint32_t)(nt * 8) * ROWB + koff);
#pragma unroll
                for (int mt = 0; mt < 4; mt++) MMA_BF16(acc[mt][nt], ah[mt], blf);
            }
        }
        __syncthreads();
    }

    // ---------------- epilogue: smem transpose [n][m], stores + GN stats -----
    float* sf = reinterpret_cast<float*>(smem);
    int rl = lane >> 2;
    int cl2 = (lane & 3) * 2;
#pragma unroll
    for (int mt = 0; mt < 4; mt++) {
#pragma unroll
        for (int nt = 0; nt < 4; nt++) {
            int m = mwarp * 64 + mt * 16 + rl;
            int n = nwarp * 32 + nt * 8 + cl2;
            sf[n * 132 + m] = acc[mt][nt][0];
            sf[(n + 1) * 132 + m] = acc[mt][nt][1];
            sf[n * 132 + m + 8] = acc[mt][nt][2];
            sf[(n + 1) * 132 + m + 8] = acc[mt][nt][3];
        }
    }
    __syncthreads();

    float* Cp = g_tmp + ((size_t)b * C + n0) * HW + p0;
#pragma unroll
    for (int t = 0; t < 16; t++) {
        int idx = tid + t * 256;
        int n = idx >> 5;  // constant within a warp
        int ms = (idx & 31) * 4;
        float4 v = *reinterpret_cast<const float4*>(sf + n * 132 + ms);
        *reinterpret_cast<float4*>(Cp + (size_t)n * HW + ms) = v;

        float s1 = v.x + v.y + v.z + v.w;
        float s2 = v.x * v.x + v.y * v.y + v.z * v.z + v.w * v.w;
#pragma unroll
        for (int o = 16; o > 0; o >>= 1) {
            s1 += __shfl_xor_sync(0xffffffffu, s1, o);
            s2 += __shfl_xor_sync(0xffffffffu, s2, o);
        }
        if (lane == 0) {
            int bg = b * G + ((n0 + n) >> 3);
            atomicAdd(&g_stat[bg * 2], s1);
            atomicAdd(&g_stat[bg * 2 + 1], s2);
        }
    }
}

// ---------------- GroupNorm apply (+ReLU, optional residual) -----------------
// Stats come precomputed from the GEMM epilogue (g_stat).
__global__ __launch_bounds__(256) void gn_kernel(const float* __restrict__ gamma,
                                                 const float* __restrict__ beta,
                                                 const float* __restrict__ residual,
                                                 float* __restrict__ outp,
                                                 int use_internal) {
    int bg = blockIdx.x;
    int b = bg >> 5;
    int g = bg & 31;
    size_t chan_off = ((size_t)b * C + (size_t)g * 8) * HW;
    const float4* in4 = reinterpret_cast<const float4*>(g_tmp + chan_off);

    __shared__ float stats[2];
    if (threadIdx.x == 0) {
        float inv_n = 1.f / 32768.f;
        float mu = g_stat[bg * 2] * inv_n;
        stats[0] = mu;
        stats[1] = rsqrtf(g_stat[bg * 2 + 1] * inv_n - mu * mu + 1e-5f);
    }
    __syncthreads();
    float mu = stats[0], rstd = stats[1];

    int tid = threadIdx.x;
    float* dst = (use_internal ? g_act : outp) + chan_off;
    float4* out4 = reinterpret_cast<float4*>(dst);
    const float4* res4 =
        residual ? reinterpret_cast<const float4*>(residual + chan_off) : nullptr;

    for (int i = tid; i < 8 * HW / 4; i += 256) {
        int c = g * 8 + (i >> 10);
        float gm = gamma[c] * rstd;
        float bt = beta[c] - mu * gm;
        float4 v = in4[i];
        v.x = v.x * gm + bt;
        v.y = v.y * gm + bt;
        v.z = v.z * gm + bt;
        v.w = v.w * gm + bt;
        if (res4) {
            float4 r = res4[i];
            v.x += r.x; v.y += r.y; v.z += r.z; v.w += r.w;
        }
        v.x = fmaxf(v.x, 0.f);
        v.y = fmaxf(v.y, 0.f);
        v.z = fmaxf(v.z, 0.f);
        v.w = fmaxf(v.w, 0.f);
        out4[i] = v;
    }
}

// ---------------- launcher ---------------------------------------------------
extern "C" void kernel_launch(void* const* d_in, const int* in_sizes, int n_in,
                              void* d_out, int out_size) {
    const float* x      = (const float*)d_in[0];
    const float* w_off1 = (const float*)d_in[1];
    const float* b_off1 = (const float*)d_in[2];
    const float* w_off2 = (const float*)d_in[3];
    const float* b_off2 = (const float*)d_in[4];
    const float* w_def1 = (const float*)d_in[5];
    const float* w_def2 = (const float*)d_in[6];
    const float* gamma1 = (const float*)d_in[7];
    const float* beta1  = (const float*)d_in[8];
    const float* gamma2 = (const float*)d_in[9];
    const float* beta2  = (const float*)d_in[10];
    float* out = (float*)d_out;

    cudaFuncSetAttribute(mma_gemm_kernel, cudaFuncAttributeMaxDynamicSharedMemorySize,
                         GSMEM);

    dim3 conv_grid(4, 4, BB * 4);
    dim3 gath_grid(HW / 256, KK, BB * 4);
    dim3 gemm_grid(HW / 128, C / 128, BB);
    int init_blocks = (BB * OC_OFF * HW + 255) / 256;
    int wprep_blocks = (2 * C * CK + 255) / 256;

    wprep_kernel<<<wprep_blocks, 256>>>(w_def1, w_def2);

    // ---- stage 1 ----
    init_offset_kernel<<<init_blocks, 256>>>(b_off1);
    offset_conv_kernel<<<conv_grid, 256>>>(x, w_off1, 0);
    gather_kernel<<<gath_grid, 256>>>(x, 0);
    mma_gemm_kernel<<<gemm_grid, 256, GSMEM>>>(0);
    gn_kernel<<<BB * G, 256>>>(gamma1, beta1, nullptr, nullptr, 1);

    // ---- stage 2 ----
    init_offset_kernel<<<init_blocks, 256>>>(b_off2);
    offset_conv_kernel<<<conv_grid, 256>>>(nullptr, w_off2, 1);
    gather_kernel<<<gath_grid, 256>>>(nullptr, 1);
    mma_gemm_kernel<<<gemm_grid, 256, GSMEM>>>(1);
    gn_kernel<<<BB * G, 256>>>(gamma2, beta2, x, out, 0);
}

// round 8
// speedup vs baseline: 1.3360x; 1.3360x over previous
#include <cuda_runtime.h>
#include <cuda_fp16.h>
#include <cstdint>

#define BB 4
#define C 256
#define H 64
#define W 64
#define HW 4096
#define G 32
#define KK 9
#define OC_OFF 18
#define CK 2304  /* C * KK */

// ---------------- device scratch (static, no runtime allocation) -------------
__device__ float g_offset[BB * OC_OFF * HW];                      // 1.18 MB
__device__ __align__(16) __half g_val[(size_t)BB * HW * CK];      // 75.5 MB
__device__ __align__(16) __half g_wh[2 * C * CK];                 // 2.36 MB
__device__ __align__(16) __half g_wl[2 * C * CK];                 // 2.36 MB
__device__ float g_tmp[(size_t)BB * C * HW];                      // 16.8 MB
__device__ float g_act[(size_t)BB * C * HW];                      // 16.8 MB
__device__ float g_stat[BB * G * 2];                              // group sums

// ---------------- helpers ----------------------------------------------------
__device__ __forceinline__ uint32_t smem_u32(const void* p) {
    uint32_t a;
    asm("{ .reg .u64 t; cvta.to.shared.u64 t, %1; cvt.u32.u64 %0, t; }"
        : "=r"(a) : "l"(p));
    return a;
}
__device__ __forceinline__ void cp16(uint32_t saddr, const void* gaddr) {
    asm volatile("cp.async.cg.shared.global [%0], [%1], 16;"
                 :: "r"(saddr), "l"(gaddr));
}

#define MMA_F16(d, a, bfr)                                                   \
    asm volatile(                                                            \
        "mma.sync.aligned.m16n8k16.row.col.f32.f16.f16.f32 "                 \
        "{%0,%1,%2,%3}, {%4,%5,%6,%7}, {%8,%9}, {%0,%1,%2,%3};"              \
        : "+f"((d)[0]), "+f"((d)[1]), "+f"((d)[2]), "+f"((d)[3])             \
        : "r"((a)[0]), "r"((a)[1]), "r"((a)[2]), "r"((a)[3]),                \
          "r"((bfr)[0]), "r"((bfr)[1]))

#define LDSM_X4(fr, addr)                                                    \
    asm volatile("ldmatrix.sync.aligned.m8n8.x4.shared.b16 "                 \
                 "{%0,%1,%2,%3}, [%4];"                                      \
                 : "=r"((fr)[0]), "=r"((fr)[1]), "=r"((fr)[2]), "=r"((fr)[3])\
                 : "r"(addr))

#define LDSM_X2(fr, addr)                                                    \
    asm volatile("ldmatrix.sync.aligned.m8n8.x2.shared.b16 {%0,%1}, [%2];"   \
                 : "=r"((fr)[0]), "=r"((fr)[1]) : "r"(addr))

// ---------------- init offset buffer with bias + clear group stats -----------
__global__ void init_offset_kernel(const float* __restrict__ bias) {
    int i = blockIdx.x * 256 + threadIdx.x;
    if (blockIdx.x == 0 && threadIdx.x < BB * G * 2) g_stat[threadIdx.x] = 0.f;
    if (i < BB * OC_OFF * HW) {
        int oc = (i / HW) % OC_OFF;
        g_offset[i] = bias[oc];
    }
}

// ---------------- weight split/reorder: w[oc][cin][k] -> [oc][k*256+cin] -----
__global__ void wprep_kernel(const float* __restrict__ w1, const float* __restrict__ w2) {
    int i = blockIdx.x * 256 + threadIdx.x;
    if (i >= 2 * C * CK) return;
    int s = i / (C * CK);
    int rem = i - s * (C * CK);
    int oc = rem / CK;
    int r = rem - oc * CK;
    int k = r >> 8;
    int cin = r & 255;
    const float* w = s ? w2 : w1;
    float v = w[(size_t)oc * CK + cin * 9 + k];
    __half h = __float2half(v);
    g_wh[i] = h;
    g_wl[i] = __float2half(v - __half2float(h));
}

// ---------------- offset conv3x3: C in -> 18 out, pad 1 ----------------------
#define CIN_CHUNK 64
__global__ __launch_bounds__(256) void offset_conv_kernel(
    const float* __restrict__ xin, const float* __restrict__ woff, int use_internal) {
    __shared__ __align__(16) float ws[CIN_CHUNK * 9 * 20];
    __shared__ float xs[18 * 18];

    int tid = threadIdx.x;
    int bz = blockIdx.z;
    int b = bz >> 2;
    int chunk = bz & 3;
    int cin0 = chunk * CIN_CHUNK;

    for (int idx = tid; idx < CIN_CHUNK * 9 * 18; idx += 256) {
        int cl = idx / 162;
        int rem = idx - cl * 162;
        int k = rem / 18;
        int oc = rem - k * 18;
        ws[(cl * 9 + k) * 20 + oc] =
            woff[(size_t)oc * (C * 9) + (size_t)(cin0 + cl) * 9 + k];
    }

    int ty = tid >> 4, tx = tid & 15;
    int py0 = blockIdx.y * 16, px0 = blockIdx.x * 16;

    float acc[18];
#pragma unroll
    for (int i = 0; i < 18; i++) acc[i] = 0.f;

    const float* src = use_internal ? g_act : xin;
    const float* xb = src + ((size_t)b * C + cin0) * HW;

    __syncthreads();

    for (int cl = 0; cl < CIN_CHUNK; cl++) {
        const float* xc = xb + (size_t)cl * HW;
        for (int idx = tid; idx < 324; idx += 256) {
            int r = idx / 18, cc = idx - r * 18;
            int gy = py0 - 1 + r, gx = px0 - 1 + cc;
            float v = 0.f;
            if (gy >= 0 && gy < H && gx >= 0 && gx < W) v = xc[gy * W + gx];
            xs[idx] = v;
        }
        __syncthreads();

        float xv[9];
#pragma unroll
        for (int ky = 0; ky < 3; ky++)
#pragma unroll
            for (int kx = 0; kx < 3; kx++)
                xv[ky * 3 + kx] = xs[(ty + ky) * 18 + (tx + kx)];

#pragma unroll
        for (int k = 0; k < 9; k++) {
            const float* wr = &ws[(cl * 9 + k) * 20];
            float xk = xv[k];
#pragma unroll
            for (int oc = 0; oc < 18; oc++) acc[oc] += xk * wr[oc];
        }
        __syncthreads();
    }

    int p = (py0 + ty) * W + (px0 + tx);
    float* ob = g_offset + (size_t)b * OC_OFF * HW + p;
#pragma unroll
    for (int oc = 0; oc < 18; oc++) atomicAdd(ob + (size_t)oc * HW, acc[oc]);
}

// ---------------- bilinear gather -> val[b][p][k*256+cin] (fp16) -------------
// grid (16, 9, B*4): z = b*4 + channel chunk of 64. One thread per pixel.
// 16-channel groups: all 64 corner loads issued before any consumption (MLP).
__global__ __launch_bounds__(256) void gather_kernel(const float* __restrict__ xin,
                                                     int use_internal) {
    int tid = threadIdx.x;
    int p = blockIdx.x * 256 + tid;
    int k = blockIdx.y;
    int b = blockIdx.z >> 2;
    int cin0 = (blockIdx.z & 3) * 64;
    int h = p >> 6, w = p & 63;

    const float* off = g_offset + ((size_t)b * OC_OFF + 2 * k) * HW + p;
    float dy = off[0];
    float dx = off[HW];
    int ky = k / 3, kx = k - ky * 3;

    float py = dy + (float)(h - 1 + ky);
    float px = dx + (float)(w - 1 + kx);
    float fy = floorf(py), fx = floorf(px);
    int iy0 = (int)fy, ix0 = (int)fx;
    float ly = py - fy, lx = px - fx;

    float vy0 = (iy0 >= 0 && iy0 < H) ? 1.f : 0.f;
    float vy1 = (iy0 + 1 >= 0 && iy0 + 1 < H) ? 1.f : 0.f;
    float vx0 = (ix0 >= 0 && ix0 < W) ? 1.f : 0.f;
    float vx1 = (ix0 + 1 >= 0 && ix0 + 1 < W) ? 1.f : 0.f;

    float w00 = (1.f - ly) * (1.f - lx) * vy0 * vx0;
    float w01 = (1.f - ly) * lx * vy0 * vx1;
    float w10 = ly * (1.f - lx) * vy1 * vx0;
    float w11 = ly * lx * vy1 * vx1;

    int cy0 = min(max(iy0, 0), H - 1);
    int cy1 = min(max(iy0 + 1, 0), H - 1);
    int cx0 = min(max(ix0, 0), W - 1);
    int cx1 = min(max(ix0 + 1, 0), W - 1);
    int i00 = cy0 * W + cx0, i01 = cy0 * W + cx1;
    int i10 = cy1 * W + cx0, i11 = cy1 * W + cx1;

    const float* src = use_internal ? g_act : xin;
    const float* xb = src + (size_t)b * C * HW;
    __half* vo = g_val + ((size_t)b * HW + p) * CK + (size_t)k * 256;

#pragma unroll 1
    for (int c0 = cin0; c0 < cin0 + 64; c0 += 16) {
        const float* xc = xb + (size_t)c0 * HW;
        float v00[16], v01[16], v10[16], v11[16];
#pragma unroll
        for (int j = 0; j < 16; j++) v00[j] = __ldg(xc + (size_t)j * HW + i00);
#pragma unroll
        for (int j = 0; j < 16; j++) v01[j] = __ldg(xc + (size_t)j * HW + i01);
#pragma unroll
        for (int j = 0; j < 16; j++) v10[j] = __ldg(xc + (size_t)j * HW + i10);
#pragma unroll
        for (int j = 0; j < 16; j++) v11[j] = __ldg(xc + (size_t)j * HW + i11);

        __align__(16) __half hb[16];
#pragma unroll
        for (int j = 0; j < 16; j++) {
            float s = w00 * v00[j] + w01 * v01[j] + w10 * v10[j] + w11 * v11[j];
            hb[j] = __float2half(s);
        }
        *reinterpret_cast<uint4*>(vo + c0) = *reinterpret_cast<const uint4*>(hb);
        *reinterpret_cast<uint4*>(vo + c0 + 8) =
            *reinterpret_cast<const uint4*>(hb + 8);
    }
}

// ---------------- HMMA GEMM: D[p, oc] = sum_r val[p][r] * W[oc][r] -----------
// CTA tile 128(pixels) x 128(oc). fp16 2-term: A*Wh + A*Wl, fp32 accum.
// 3-stage cp.async pipeline, single __syncthreads per chunk.
// Rows padded to 80B (stride 5x16B coprime with 8 -> conflict-free ldmatrix).
#define KC 32
#define NKC (CK / KC) /* 72 */
#define ROWB 80
#define A_OFF 0
#define BH_OFF (128 * ROWB)
#define BL_OFF (2 * 128 * ROWB)
#define STGSZ (3 * 128 * ROWB) /* 30720 */
#define GSMEM (3 * STGSZ)      /* 92160 */

__global__ __launch_bounds__(256, 2) void mma_gemm_kernel(int stage) {
    extern __shared__ __align__(16) char smem[];
    uint32_t sb = smem_u32(smem);
    int tid = threadIdx.x;
    int wid = tid >> 5, lane = tid & 31;
    int b = blockIdx.z;
    int n0 = blockIdx.y * 128;
    int p0 = blockIdx.x * 128;

    const __half* Ag = g_val + ((size_t)b * HW + p0) * CK;
    const __half* Bh = g_wh + ((size_t)stage * C + n0) * CK;
    const __half* Bl = g_wl + ((size_t)stage * C + n0) * CK;

    // A: 2 threads/row, 32B each. B: thread t -> plane t>>7, row t&127, 64B.
    int arow = tid >> 1;
    int aseg = tid & 1;
    size_t agoff = (size_t)arow * CK + aseg * 16;
    uint32_t asoff = (uint32_t)arow * ROWB + (uint32_t)aseg * 32;
    int bplane = tid >> 7;
    int brow = tid & 127;
    const __half* Bg = (bplane ? Bl : Bh) + (size_t)brow * CK;
    uint32_t bsoff = (bplane ? BL_OFF : BH_OFF) + (uint32_t)brow * ROWB;

    int mwarp = wid >> 2, nwarp = wid & 3;
    uint32_t aoff = (uint32_t)(mwarp * 64 + (lane & 15)) * ROWB + (lane >> 4) * 16;
    uint32_t boff = (uint32_t)(nwarp * 32 + (lane & 7)) * ROWB + ((lane >> 3) & 1) * 16;

    float acc[4][4][4];
#pragma unroll
    for (int i = 0; i < 4; i++)
#pragma unroll
        for (int j = 0; j < 4; j++)
#pragma unroll
            for (int q = 0; q < 4; q++) acc[i][j][q] = 0.f;

    // prologue: stages 0,1
#pragma unroll
    for (int s = 0; s < 2; s++) {
        uint32_t stb = sb + (uint32_t)s * STGSZ;
        int kc = s * KC;
        cp16(stb + A_OFF + asoff, Ag + agoff + kc);
        cp16(stb + A_OFF + asoff + 16, Ag + agoff + kc + 8);
#pragma unroll
        for (int j = 0; j < 4; j++)
            cp16(stb + bsoff + j * 16, Bg + kc + j * 8);
        asm volatile("cp.async.commit_group;" ::: "memory");
    }

#pragma unroll 1
    for (int i = 0; i < NKC; i++) {
        asm volatile("cp.async.wait_group 1;" ::: "memory");
        __syncthreads();

        // issue stage i+2 into buffer (i+2)%3 (safe: all warps passed compute i-1)
        if (i + 2 < NKC) {
            uint32_t stb = sb + (uint32_t)((i + 2) % 3) * STGSZ;
            int kc = (i + 2) * KC;
            cp16(stb + A_OFF + asoff, Ag + agoff + kc);
            cp16(stb + A_OFF + asoff + 16, Ag + agoff + kc + 8);
#pragma unroll
            for (int j = 0; j < 4; j++)
                cp16(stb + bsoff + j * 16, Bg + kc + j * 8);
        }
        asm volatile("cp.async.commit_group;" ::: "memory");

        uint32_t cb = sb + (uint32_t)(i % 3) * STGSZ;
#pragma unroll
        for (int kk = 0; kk < 2; kk++) {
            uint32_t koff = (uint32_t)kk * 32;
            uint32_t ah[4][4], bb[4][2];
#pragma unroll
            for (int mt = 0; mt < 4; mt++)
                LDSM_X4(ah[mt], cb + A_OFF + aoff + (uint32_t)(mt * 16) * ROWB + koff);
#pragma unroll
            for (int nt = 0; nt < 4; nt++)
                LDSM_X2(bb[nt], cb + BH_OFF + boff + (uint32_t)(nt * 8) * ROWB + koff);
#pragma unroll
            for (int mt = 0; mt < 4; mt++)
#pragma unroll
                for (int nt = 0; nt < 4; nt++) MMA_F16(acc[mt][nt], ah[mt], bb[nt]);
#pragma unroll
            for (int nt = 0; nt < 4; nt++)
                LDSM_X2(bb[nt], cb + BL_OFF + boff + (uint32_t)(nt * 8) * ROWB + koff);
#pragma unroll
            for (int mt = 0; mt < 4; mt++)
#pragma unroll
                for (int nt = 0; nt < 4; nt++) MMA_F16(acc[mt][nt], ah[mt], bb[nt]);
        }
    }
    __syncthreads();

    // ---------------- epilogue: smem transpose [n][m], stores + GN stats -----
    float* sf = reinterpret_cast<float*>(smem);
    int rl = lane >> 2;
    int cl2 = (lane & 3) * 2;
#pragma unroll
    for (int mt = 0; mt < 4; mt++) {
#pragma unroll
        for (int nt = 0; nt < 4; nt++) {
            int m = mwarp * 64 + mt * 16 + rl;
            int n = nwarp * 32 + nt * 8 + cl2;
            sf[n * 132 + m] = acc[mt][nt][0];
            sf[(n + 1) * 132 + m] = acc[mt][nt][1];
            sf[n * 132 + m + 8] = acc[mt][nt][2];
            sf[(n + 1) * 132 + m + 8] = acc[mt][nt][3];
        }
    }
    __syncthreads();

    float* Cp = g_tmp + ((size_t)b * C + n0) * HW + p0;
#pragma unroll
    for (int t = 0; t < 16; t++) {
        int idx = tid + t * 256;
        int n = idx >> 5;  // constant within a warp
        int ms = (idx & 31) * 4;
        float4 v = *reinterpret_cast<const float4*>(sf + n * 132 + ms);
        *reinterpret_cast<float4*>(Cp + (size_t)n * HW + ms) = v;

        float s1 = v.x + v.y + v.z + v.w;
        float s2 = v.x * v.x + v.y * v.y + v.z * v.z + v.w * v.w;
#pragma unroll
        for (int o = 16; o > 0; o >>= 1) {
            s1 += __shfl_xor_sync(0xffffffffu, s1, o);
            s2 += __shfl_xor_sync(0xffffffffu, s2, o);
        }
        if (lane == 0) {
            int bg = b * G + ((n0 + n) >> 3);
            atomicAdd(&g_stat[bg * 2], s1);
            atomicAdd(&g_stat[bg * 2 + 1], s2);
        }
    }
}

// ---------------- GroupNorm apply (+ReLU, optional residual) -----------------
__global__ __launch_bounds__(256) void gn_kernel(const float* __restrict__ gamma,
                                                 const float* __restrict__ beta,
                                                 const float* __restrict__ residual,
                                                 float* __restrict__ outp,
                                                 int use_internal) {
    int bg = blockIdx.x;
    int b = bg >> 5;
    int g = bg & 31;
    size_t chan_off = ((size_t)b * C + (size_t)g * 8) * HW;
    const float4* in4 = reinterpret_cast<const float4*>(g_tmp + chan_off);

    __shared__ float stats[2];
    if (threadIdx.x == 0) {
        float inv_n = 1.f / 32768.f;
        float mu = g_stat[bg * 2] * inv_n;
        stats[0] = mu;
        stats[1] = rsqrtf(g_stat[bg * 2 + 1] * inv_n - mu * mu + 1e-5f);
    }
    __syncthreads();
    float mu = stats[0], rstd = stats[1];

    int tid = threadIdx.x;
    float* dst = (use_internal ? g_act : outp) + chan_off;
    float4* out4 = reinterpret_cast<float4*>(dst);
    const float4* res4 =
        residual ? reinterpret_cast<const float4*>(residual + chan_off) : nullptr;

    for (int i = tid; i < 8 * HW / 4; i += 256) {
        int c = g * 8 + (i >> 10);
        float gm = gamma[c] * rstd;
        float bt = beta[c] - mu * gm;
        float4 v = in4[i];
        v.x = v.x * gm + bt;
        v.y = v.y * gm + bt;
        v.z = v.z * gm + bt;
        v.w = v.w * gm + bt;
        if (res4) {
            float4 r = res4[i];
            v.x += r.x; v.y += r.y; v.z += r.z; v.w += r.w;
        }
        v.x = fmaxf(v.x, 0.f);
        v.y = fmaxf(v.y, 0.f);
        v.z = fmaxf(v.z, 0.f);
        v.w = fmaxf(v.w, 0.f);
        out4[i] = v;
    }
}

// ---------------- launcher ---------------------------------------------------
extern "C" void kernel_launch(void* const* d_in, const int* in_sizes, int n_in,
                              void* d_out, int out_size) {
    const float* x      = (const float*)d_in[0];
    const float* w_off1 = (const float*)d_in[1];
    const float* b_off1 = (const float*)d_in[2];
    const float* w_off2 = (const float*)d_in[3];
    const float* b_off2 = (const float*)d_in[4];
    const float* w_def1 = (const float*)d_in[5];
    const float* w_def2 = (const float*)d_in[6];
    const float* gamma1 = (const float*)d_in[7];
    const float* beta1  = (const float*)d_in[8];
    const float* gamma2 = (const float*)d_in[9];
    const float* beta2  = (const float*)d_in[10];
    float* out = (float*)d_out;

    cudaFuncSetAttribute(mma_gemm_kernel, cudaFuncAttributeMaxDynamicSharedMemorySize,
                         GSMEM);

    dim3 conv_grid(4, 4, BB * 4);
    dim3 gath_grid(HW / 256, KK, BB * 4);
    dim3 gemm_grid(HW / 128, C / 128, BB);
    int init_blocks = (BB * OC_OFF * HW + 255) / 256;
    int wprep_blocks = (2 * C * CK + 255) / 256;

    wprep_kernel<<<wprep_blocks, 256>>>(w_def1, w_def2);

    // ---- stage 1 ----
    init_offset_kernel<<<init_blocks, 256>>>(b_off1);
    offset_conv_kernel<<<conv_grid, 256>>>(x, w_off1, 0);
    gather_kernel<<<gath_grid, 256>>>(x, 0);
    mma_gemm_kernel<<<gemm_grid, 256, GSMEM>>>(0);
    gn_kernel<<<BB * G, 256>>>(gamma1, beta1, nullptr, nullptr, 1);

    // ---- stage 2 ----
    init_offset_kernel<<<init_blocks, 256>>>(b_off2);
    offset_conv_kernel<<<conv_grid, 256>>>(nullptr, w_off2, 1);
    gather_kernel<<<gath_grid, 256>>>(nullptr, 1);
    mma_gemm_kernel<<<gemm_grid, 256, GSMEM>>>(1);
    gn_kernel<<<BB * G, 256>>>(gamma2, beta2, x, out, 0);
}

// round 9
// speedup vs baseline: 1.4124x; 1.0572x over previous
#include <cuda_runtime.h>
#include <cuda_fp16.h>
#include <cstdint>

#define BB 4
#define C 256
#define H 64
#define W 64
#define HW 4096
#define G 32
#define KK 9
#define OC_OFF 18
#define CK 2304  /* C * KK */

// ---------------- device scratch (static, no runtime allocation) -------------
__device__ float g_offset[BB * OC_OFF * HW];                      // 1.18 MB
__device__ __align__(16) __half g_val[(size_t)BB * HW * CK];      // 75.5 MB
__device__ __align__(16) __half g_wh[2 * C * CK];                 // 2.36 MB
__device__ __align__(16) __half g_wl[2 * C * CK];                 // 2.36 MB
__device__ float g_tmp[(size_t)BB * C * HW];                      // 16.8 MB
__device__ float g_act[(size_t)BB * C * HW];                      // 16.8 MB
__device__ float g_stat[BB * G * 2];                              // group sums

// ---------------- helpers ----------------------------------------------------
__device__ __forceinline__ uint32_t smem_u32(const void* p) {
    uint32_t a;
    asm("{ .reg .u64 t; cvta.to.shared.u64 t, %1; cvt.u32.u64 %0, t; }"
        : "=r"(a) : "l"(p));
    return a;
}
__device__ __forceinline__ void cp16(uint32_t saddr, const void* gaddr) {
    asm volatile("cp.async.cg.shared.global [%0], [%1], 16;"
                 :: "r"(saddr), "l"(gaddr));
}

#define MMA_F16(d, a, bfr)                                                   \
    asm volatile(                                                            \
        "mma.sync.aligned.m16n8k16.row.col.f32.f16.f16.f32 "                 \
        "{%0,%1,%2,%3}, {%4,%5,%6,%7}, {%8,%9}, {%0,%1,%2,%3};"              \
        : "+f"((d)[0]), "+f"((d)[1]), "+f"((d)[2]), "+f"((d)[3])             \
        : "r"((a)[0]), "r"((a)[1]), "r"((a)[2]), "r"((a)[3]),                \
          "r"((bfr)[0]), "r"((bfr)[1]))

#define LDSM_X4(fr, addr)                                                    \
    asm volatile("ldmatrix.sync.aligned.m8n8.x4.shared.b16 "                 \
                 "{%0,%1,%2,%3}, [%4];"                                      \
                 : "=r"((fr)[0]), "=r"((fr)[1]), "=r"((fr)[2]), "=r"((fr)[3])\
                 : "r"(addr))

// ---------------- init offset buffer with bias + clear group stats -----------
__global__ void init_offset_kernel(const float* __restrict__ bias) {
    int i = blockIdx.x * 256 + threadIdx.x;
    if (blockIdx.x == 0 && threadIdx.x < BB * G * 2) g_stat[threadIdx.x] = 0.f;
    if (i < BB * OC_OFF * HW) {
        int oc = (i / HW) % OC_OFF;
        g_offset[i] = bias[oc];
    }
}

// ---------------- weight split/reorder: w[oc][cin][k] -> [oc][k*256+cin] -----
__global__ void wprep_kernel(const float* __restrict__ w1, const float* __restrict__ w2) {
    int i = blockIdx.x * 256 + threadIdx.x;
    if (i >= 2 * C * CK) return;
    int s = i / (C * CK);
    int rem = i - s * (C * CK);
    int oc = rem / CK;
    int r = rem - oc * CK;
    int k = r >> 8;
    int cin = r & 255;
    const float* w = s ? w2 : w1;
    float v = w[(size_t)oc * CK + cin * 9 + k];
    __half h = __float2half(v);
    g_wh[i] = h;
    g_wl[i] = __float2half(v - __half2float(h));
}

// ---------------- offset conv3x3: C in -> 18 out, pad 1 ----------------------
// Double-buffered halo tile: load cl+1 while computing cl (hides LDG latency).
#define CIN_CHUNK 64
__global__ __launch_bounds__(256) void offset_conv_kernel(
    const float* __restrict__ xin, const float* __restrict__ woff, int use_internal) {
    __shared__ __align__(16) float ws[CIN_CHUNK * 9 * 20];
    __shared__ float xs[2][18 * 18];

    int tid = threadIdx.x;
    int bz = blockIdx.z;
    int b = bz >> 2;
    int chunk = bz & 3;
    int cin0 = chunk * CIN_CHUNK;

    for (int idx = tid; idx < CIN_CHUNK * 9 * 18; idx += 256) {
        int cl = idx / 162;
        int rem = idx - cl * 162;
        int k = rem / 18;
        int oc = rem - k * 18;
        ws[(cl * 9 + k) * 20 + oc] =
            woff[(size_t)oc * (C * 9) + (size_t)(cin0 + cl) * 9 + k];
    }

    int ty = tid >> 4, tx = tid & 15;
    int py0 = blockIdx.y * 16, px0 = blockIdx.x * 16;

    float acc[18];
#pragma unroll
    for (int i = 0; i < 18; i++) acc[i] = 0.f;

    const float* src = use_internal ? g_act : xin;
    const float* xb = src + ((size_t)b * C + cin0) * HW;

    // each thread owns at most 2 halo slots (324 over 256 threads)
    int hidx0 = tid;
    int hidx1 = tid + 256;
    int hr0 = hidx0 / 18, hc0 = hidx0 - hr0 * 18;
    int hr1 = hidx1 / 18, hc1 = hidx1 - hr1 * 18;
    int gy0 = py0 - 1 + hr0, gx0 = px0 - 1 + hc0;
    int gy1 = py0 - 1 + hr1, gx1 = px0 - 1 + hc1;
    bool v0 = (gy0 >= 0 && gy0 < H && gx0 >= 0 && gx0 < W);
    bool v1 = (hidx1 < 324) && (gy1 >= 0 && gy1 < H && gx1 >= 0 && gx1 < W);
    int go0 = gy0 * W + gx0, go1 = gy1 * W + gx1;

    // preload channel 0
    {
        const float* xc = xb;
        xs[0][hidx0] = v0 ? xc[go0] : 0.f;
        if (hidx1 < 324) xs[0][hidx1] = v1 ? xc[go1] : 0.f;
    }
    __syncthreads();

#pragma unroll 1
    for (int cl = 0; cl < CIN_CHUNK; cl++) {
        int cur = cl & 1;
        // prefetch next channel halo into other buffer
        if (cl + 1 < CIN_CHUNK) {
            const float* xn = xb + (size_t)(cl + 1) * HW;
            xs[cur ^ 1][hidx0] = v0 ? __ldg(xn + go0) : 0.f;
            if (hidx1 < 324) xs[cur ^ 1][hidx1] = v1 ? __ldg(xn + go1) : 0.f;
        }

        float xv[9];
#pragma unroll
        for (int ky = 0; ky < 3; ky++)
#pragma unroll
            for (int kx = 0; kx < 3; kx++)
                xv[ky * 3 + kx] = xs[cur][(ty + ky) * 18 + (tx + kx)];

#pragma unroll
        for (int k = 0; k < 9; k++) {
            const float* wr = &ws[(cl * 9 + k) * 20];
            float xk = xv[k];
#pragma unroll
            for (int oc = 0; oc < 18; oc++) acc[oc] += xk * wr[oc];
        }
        __syncthreads();
    }

    int p = (py0 + ty) * W + (px0 + tx);
    float* ob = g_offset + (size_t)b * OC_OFF * HW + p;
#pragma unroll
    for (int oc = 0; oc < 18; oc++) atomicAdd(ob + (size_t)oc * HW, acc[oc]);
}

// ---------------- bilinear gather -> val[b][p][k*256+cin] (fp16) -------------
// grid (16, 9, B*4): z = b*4 + channel chunk of 64. One thread per pixel.
__global__ __launch_bounds__(256) void gather_kernel(const float* __restrict__ xin,
                                                     int use_internal) {
    int tid = threadIdx.x;
    int p = blockIdx.x * 256 + tid;
    int k = blockIdx.y;
    int b = blockIdx.z >> 2;
    int cin0 = (blockIdx.z & 3) * 64;
    int h = p >> 6, w = p & 63;

    const float* off = g_offset + ((size_t)b * OC_OFF + 2 * k) * HW + p;
    float dy = off[0];
    float dx = off[HW];
    int ky = k / 3, kx = k - ky * 3;

    float py = dy + (float)(h - 1 + ky);
    float px = dx + (float)(w - 1 + kx);
    float fy = floorf(py), fx = floorf(px);
    int iy0 = (int)fy, ix0 = (int)fx;
    float ly = py - fy, lx = px - fx;

    float vy0 = (iy0 >= 0 && iy0 < H) ? 1.f : 0.f;
    float vy1 = (iy0 + 1 >= 0 && iy0 + 1 < H) ? 1.f : 0.f;
    float vx0 = (ix0 >= 0 && ix0 < W) ? 1.f : 0.f;
    float vx1 = (ix0 + 1 >= 0 && ix0 + 1 < W) ? 1.f : 0.f;

    float w00 = (1.f - ly) * (1.f - lx) * vy0 * vx0;
    float w01 = (1.f - ly) * lx * vy0 * vx1;
    float w10 = ly * (1.f - lx) * vy1 * vx0;
    float w11 = ly * lx * vy1 * vx1;

    int cy0 = min(max(iy0, 0), H - 1);
    int cy1 = min(max(iy0 + 1, 0), H - 1);
    int cx0 = min(max(ix0, 0), W - 1);
    int cx1 = min(max(ix0 + 1, 0), W - 1);
    int i00 = cy0 * W + cx0, i01 = cy0 * W + cx1;
    int i10 = cy1 * W + cx0, i11 = cy1 * W + cx1;

    const float* src = use_internal ? g_act : xin;
    const float* xb = src + (size_t)b * C * HW;
    __half* vo = g_val + ((size_t)b * HW + p) * CK + (size_t)k * 256;

#pragma unroll 1
    for (int c0 = cin0; c0 < cin0 + 64; c0 += 16) {
        const float* xc = xb + (size_t)c0 * HW;
        float v00[16], v01[16], v10[16], v11[16];
#pragma unroll
        for (int j = 0; j < 16; j++) v00[j] = __ldg(xc + (size_t)j * HW + i00);
#pragma unroll
        for (int j = 0; j < 16; j++) v01[j] = __ldg(xc + (size_t)j * HW + i01);
#pragma unroll
        for (int j = 0; j < 16; j++) v10[j] = __ldg(xc + (size_t)j * HW + i10);
#pragma unroll
        for (int j = 0; j < 16; j++) v11[j] = __ldg(xc + (size_t)j * HW + i11);

        __align__(16) __half hb[16];
#pragma unroll
        for (int j = 0; j < 16; j++) {
            float s = w00 * v00[j] + w01 * v01[j] + w10 * v10[j] + w11 * v11[j];
            hb[j] = __float2half(s);
        }
        *reinterpret_cast<uint4*>(vo + c0) = *reinterpret_cast<const uint4*>(hb);
        *reinterpret_cast<uint4*>(vo + c0 + 8) =
            *reinterpret_cast<const uint4*>(hb + 8);
    }
}

// ---------------- HMMA GEMM: D[p, oc] = sum_r val[p][r] * W[oc][r] -----------
// CTA tile 128(pixels) x 128(oc). fp16 2-term: A*Wh + A*Wl, fp32 accum.
// KC=64, 2-stage double buffer: 36 iterations (halved per-chunk fixed costs).
// Rows padded to 144B (9x16B, coprime with 8 -> conflict-free ldmatrix).
#define KC 64
#define NKC (CK / KC) /* 36 */
#define ROWB 144
#define A_OFF 0
#define BH_OFF (128 * ROWB)
#define BL_OFF (2 * 128 * ROWB)
#define STGSZ (3 * 128 * ROWB) /* 55296 */
#define GSMEM (2 * STGSZ)      /* 110592 */

__global__ __launch_bounds__(256, 2) void mma_gemm_kernel(int stage) {
    extern __shared__ __align__(16) char smem[];
    uint32_t sb = smem_u32(smem);
    int tid = threadIdx.x;
    int wid = tid >> 5, lane = tid & 31;
    int b = blockIdx.z;
    int n0 = blockIdx.y * 128;
    int p0 = blockIdx.x * 128;

    const __half* Ag = g_val + ((size_t)b * HW + p0) * CK;
    const __half* Bh = g_wh + ((size_t)stage * C + n0) * CK;
    const __half* Bl = g_wl + ((size_t)stage * C + n0) * CK;

    // A: 2 threads/row, 64B each. B: thread t -> plane t>>7, row t&127, 128B.
    int arow = tid >> 1;
    int aseg = tid & 1;
    size_t agoff = (size_t)arow * CK + aseg * 32;
    uint32_t asoff = (uint32_t)arow * ROWB + (uint32_t)aseg * 64;
    int bplane = tid >> 7;
    int brow = tid & 127;
    const __half* Bg = (bplane ? Bl : Bh) + (size_t)brow * CK;
    uint32_t bsoff = (bplane ? BL_OFF : BH_OFF) + (uint32_t)brow * ROWB;

    int mwarp = wid >> 2, nwarp = wid & 3;
    uint32_t aoff = (uint32_t)(mwarp * 64 + (lane & 15)) * ROWB + (lane >> 4) * 16;
    // B X4: lanes 0-15 -> n-rows [ntp*16, +8) k-halves; lanes 16-31 -> +8 rows
    uint32_t boff = (uint32_t)(nwarp * 32 + (lane >> 4) * 8 + (lane & 7)) * ROWB +
                    ((lane >> 3) & 1) * 16;

    float acc[4][4][4];
#pragma unroll
    for (int i = 0; i < 4; i++)
#pragma unroll
        for (int j = 0; j < 4; j++)
#pragma unroll
            for (int q = 0; q < 4; q++) acc[i][j][q] = 0.f;

    // prologue: stages 0,1
#pragma unroll
    for (int s = 0; s < 2; s++) {
        uint32_t stb = sb + (uint32_t)s * STGSZ;
        int kc = s * KC;
#pragma unroll
        for (int j = 0; j < 4; j++)
            cp16(stb + A_OFF + asoff + j * 16, Ag + agoff + kc + j * 8);
#pragma unroll
        for (int j = 0; j < 8; j++)
            cp16(stb + bsoff + j * 16, Bg + kc + j * 8);
        asm volatile("cp.async.commit_group;" ::: "memory");
    }

#pragma unroll 1
    for (int i = 0; i < NKC; i++) {
        asm volatile("cp.async.wait_group 1;" ::: "memory");
        __syncthreads();

        uint32_t cb = sb + (uint32_t)(i & 1) * STGSZ;
#pragma unroll
        for (int kk = 0; kk < 4; kk++) {
            uint32_t koff = (uint32_t)kk * 32;
            uint32_t ah[4][4], bbh[2][4], bbl[2][4];
#pragma unroll
            for (int mt = 0; mt < 4; mt++)
                LDSM_X4(ah[mt], cb + A_OFF + aoff + (uint32_t)(mt * 16) * ROWB + koff);
#pragma unroll
            for (int ntp = 0; ntp < 2; ntp++)
                LDSM_X4(bbh[ntp],
                        cb + BH_OFF + boff + (uint32_t)(ntp * 16) * ROWB + koff);
#pragma unroll
            for (int mt = 0; mt < 4; mt++)
#pragma unroll
                for (int nt = 0; nt < 4; nt++)
                    MMA_F16(acc[mt][nt], ah[mt], &bbh[nt >> 1][(nt & 1) * 2]);
#pragma unroll
            for (int ntp = 0; ntp < 2; ntp++)
                LDSM_X4(bbl[ntp],
                        cb + BL_OFF + boff + (uint32_t)(ntp * 16) * ROWB + koff);
#pragma unroll
            for (int mt = 0; mt < 4; mt++)
#pragma unroll
                for (int nt = 0; nt < 4; nt++)
                    MMA_F16(acc[mt][nt], ah[mt], &bbl[nt >> 1][(nt & 1) * 2]);
        }
        __syncthreads();

        // refill the just-computed buffer with chunk i+2
        if (i + 2 < NKC) {
            uint32_t stb = sb + (uint32_t)(i & 1) * STGSZ;
            int kc = (i + 2) * KC;
#pragma unroll
            for (int j = 0; j < 4; j++)
                cp16(stb + A_OFF + asoff + j * 16, Ag + agoff + kc + j * 8);
#pragma unroll
            for (int j = 0; j < 8; j++)
                cp16(stb + bsoff + j * 16, Bg + kc + j * 8);
        }
        asm volatile("cp.async.commit_group;" ::: "memory");
    }
    __syncthreads();

    // ---------------- epilogue: smem transpose [n][m], stores + GN stats -----
    float* sf = reinterpret_cast<float*>(smem);
    int rl = lane >> 2;
    int cl2 = (lane & 3) * 2;
#pragma unroll
    for (int mt = 0; mt < 4; mt++) {
#pragma unroll
        for (int nt = 0; nt < 4; nt++) {
            int m = mwarp * 64 + mt * 16 + rl;
            int n = nwarp * 32 + nt * 8 + cl2;
            sf[n * 132 + m] = acc[mt][nt][0];
            sf[(n + 1) * 132 + m] = acc[mt][nt][1];
            sf[n * 132 + m + 8] = acc[mt][nt][2];
            sf[(n + 1) * 132 + m + 8] = acc[mt][nt][3];
        }
    }
    __syncthreads();

    float* Cp = g_tmp + ((size_t)b * C + n0) * HW + p0;
#pragma unroll
    for (int t = 0; t < 16; t++) {
        int idx = tid + t * 256;
        int n = idx >> 5;  // constant within a warp
        int ms = (idx & 31) * 4;
        float4 v = *reinterpret_cast<const float4*>(sf + n * 132 + ms);
        *reinterpret_cast<float4*>(Cp + (size_t)n * HW + ms) = v;

        float s1 = v.x + v.y + v.z + v.w;
        float s2 = v.x * v.x + v.y * v.y + v.z * v.z + v.w * v.w;
#pragma unroll
        for (int o = 16; o > 0; o >>= 1) {
            s1 += __shfl_xor_sync(0xffffffffu, s1, o);
            s2 += __shfl_xor_sync(0xffffffffu, s2, o);
        }
        if (lane == 0) {
            int bg = b * G + ((n0 + n) >> 3);
            atomicAdd(&g_stat[bg * 2], s1);
            atomicAdd(&g_stat[bg * 2 + 1], s2);
        }
    }
}

// ---------------- GroupNorm apply (+ReLU, optional residual) -----------------
__global__ __launch_bounds__(256) void gn_kernel(const float* __restrict__ gamma,
                                                 const float* __restrict__ beta,
                                                 const float* __restrict__ residual,
                                                 float* __restrict__ outp,
                                                 int use_internal) {
    int bg = blockIdx.x;
    int b = bg >> 5;
    int g = bg & 31;
    size_t chan_off = ((size_t)b * C + (size_t)g * 8) * HW;
    const float4* in4 = reinterpret_cast<const float4*>(g_tmp + chan_off);

    __shared__ float stats[2];
    if (threadIdx.x == 0) {
        float inv_n = 1.f / 32768.f;
        float mu = g_stat[bg * 2] * inv_n;
        stats[0] = mu;
        stats[1] = rsqrtf(g_stat[bg * 2 + 1] * inv_n - mu * mu + 1e-5f);
    }
    __syncthreads();
    float mu = stats[0], rstd = stats[1];

    int tid = threadIdx.x;
    float* dst = (use_internal ? g_act : outp) + chan_off;
    float4* out4 = reinterpret_cast<float4*>(dst);
    const float4* res4 =
        residual ? reinterpret_cast<const float4*>(residual + chan_off) : nullptr;

    for (int i = tid; i < 8 * HW / 4; i += 256) {
        int c = g * 8 + (i >> 10);
        float gm = gamma[c] * rstd;
        float bt = beta[c] - mu * gm;
        float4 v = in4[i];
        v.x = v.x * gm + bt;
        v.y = v.y * gm + bt;
        v.z = v.z * gm + bt;
        v.w = v.w * gm + bt;
        if (res4) {
            float4 r = res4[i];
            v.x += r.x; v.y += r.y; v.z += r.z; v.w += r.w;
        }
        v.x = fmaxf(v.x, 0.f);
        v.y = fmaxf(v.y, 0.f);
        v.z = fmaxf(v.z, 0.f);
        v.w = fmaxf(v.w, 0.f);
        out4[i] = v;
    }
}

// ---------------- launcher ---------------------------------------------------
extern "C" void kernel_launch(void* const* d_in, const int* in_sizes, int n_in,
                              void* d_out, int out_size) {
    const float* x      = (const float*)d_in[0];
    const float* w_off1 = (const float*)d_in[1];
    const float* b_off1 = (const float*)d_in[2];
    const float* w_off2 = (const float*)d_in[3];
    const float* b_off2 = (const float*)d_in[4];
    const float* w_def1 = (const float*)d_in[5];
    const float* w_def2 = (const float*)d_in[6];
    const float* gamma1 = (const float*)d_in[7];
    const float* beta1  = (const float*)d_in[8];
    const float* gamma2 = (const float*)d_in[9];
    const float* beta2  = (const float*)d_in[10];
    float* out = (float*)d_out;

    cudaFuncSetAttribute(mma_gemm_kernel, cudaFuncAttributeMaxDynamicSharedMemorySize,
                         GSMEM);

    dim3 conv_grid(4, 4, BB * 4);
    dim3 gath_grid(HW / 256, KK, BB * 4);
    dim3 gemm_grid(HW / 128, C / 128, BB);
    int init_blocks = (BB * OC_OFF * HW + 255) / 256;
    int wprep_blocks = (2 * C * CK + 255) / 256;

    wprep_kernel<<<wprep_blocks, 256>>>(w_def1, w_def2);

    // ---- stage 1 ----
    init_offset_kernel<<<init_blocks, 256>>>(b_off1);
    offset_conv_kernel<<<conv_grid, 256>>>(x, w_off1, 0);
    gather_kernel<<<gath_grid, 256>>>(x, 0);
    mma_gemm_kernel<<<gemm_grid, 256, GSMEM>>>(0);
    gn_kernel<<<BB * G, 256>>>(gamma1, beta1, nullptr, nullptr, 1);

    // ---- stage 2 ----
    init_offset_kernel<<<init_blocks, 256>>>(b_off2);
    offset_conv_kernel<<<conv_grid, 256>>>(nullptr, w_off2, 1);
    gather_kernel<<<gath_grid, 256>>>(nullptr, 1);
    mma_gemm_kernel<<<gemm_grid, 256, GSMEM>>>(1);
    gn_kernel<<<BB * G, 256>>>(gamma2, beta2, x, out, 0);
}

// round 10
// speedup vs baseline: 1.4468x; 1.0244x over previous
#include <cuda_runtime.h>
#include <cuda_fp16.h>
#include <cstdint>

#define BB 4
#define C 256
#define H 64
#define W 64
#define HW 4096
#define G 32
#define KK 9
#define OC_OFF 18
#define CK 2304  /* C * KK */

// ---------------- device scratch (static, no runtime allocation) -------------
__device__ float g_offset[BB * OC_OFF * HW];                      // 1.18 MB
__device__ __align__(16) __half g_val[(size_t)BB * HW * CK];      // 75.5 MB
__device__ __align__(16) __half g_wh[2 * C * CK];                 // 2.36 MB
__device__ __align__(16) __half g_wl[2 * C * CK];                 // 2.36 MB
__device__ float g_tmp[(size_t)BB * C * HW];                      // 16.8 MB
__device__ float g_act[(size_t)BB * C * HW];                      // 16.8 MB
__device__ float g_stat[BB * G * 2];                              // group sums

// ---------------- helpers ----------------------------------------------------
__device__ __forceinline__ uint32_t smem_u32(const void* p) {
    uint32_t a;
    asm("{ .reg .u64 t; cvta.to.shared.u64 t, %1; cvt.u32.u64 %0, t; }"
        : "=r"(a) : "l"(p));
    return a;
}
__device__ __forceinline__ void cp16(uint32_t saddr, const void* gaddr) {
    asm volatile("cp.async.cg.shared.global [%0], [%1], 16;"
                 :: "r"(saddr), "l"(gaddr));
}

#define MMA_F16(d, a, bfr)                                                   \
    asm volatile(                                                            \
        "mma.sync.aligned.m16n8k16.row.col.f32.f16.f16.f32 "                 \
        "{%0,%1,%2,%3}, {%4,%5,%6,%7}, {%8,%9}, {%0,%1,%2,%3};"              \
        : "+f"((d)[0]), "+f"((d)[1]), "+f"((d)[2]), "+f"((d)[3])             \
        : "r"((a)[0]), "r"((a)[1]), "r"((a)[2]), "r"((a)[3]),                \
          "r"((bfr)[0]), "r"((bfr)[1]))

#define LDSM_X4(fr, addr)                                                    \
    asm volatile("ldmatrix.sync.aligned.m8n8.x4.shared.b16 "                 \
                 "{%0,%1,%2,%3}, [%4];"                                      \
                 : "=r"((fr)[0]), "=r"((fr)[1]), "=r"((fr)[2]), "=r"((fr)[3])\
                 : "r"(addr))

// ---------------- weight split/reorder + stage-1 offset init -----------------
// w[oc][cin][k] -> [oc][k*256+cin] (hi/lo fp16); also seeds g_offset with
// b_off1 and clears g_stat (folded stage-1 init to drop one launch).
__global__ void wprep_kernel(const float* __restrict__ w1, const float* __restrict__ w2,
                             const float* __restrict__ bias1) {
    int i = blockIdx.x * 256 + threadIdx.x;
    if (blockIdx.x == 0 && threadIdx.x < BB * G * 2) g_stat[threadIdx.x] = 0.f;
    if (i < BB * OC_OFF * HW) {
        int oc = (i / HW) % OC_OFF;
        g_offset[i] = bias1[oc];
    }
    if (i >= 2 * C * CK) return;
    int s = i / (C * CK);
    int rem = i - s * (C * CK);
    int oc = rem / CK;
    int r = rem - oc * CK;
    int k = r >> 8;
    int cin = r & 255;
    const float* w = s ? w2 : w1;
    float v = w[(size_t)oc * CK + cin * 9 + k];
    __half h = __float2half(v);
    g_wh[i] = h;
    g_wl[i] = __float2half(v - __half2float(h));
}

// ---------------- init offset buffer with bias + clear group stats -----------
__global__ void init_offset_kernel(const float* __restrict__ bias) {
    int i = blockIdx.x * 256 + threadIdx.x;
    if (blockIdx.x == 0 && threadIdx.x < BB * G * 2) g_stat[threadIdx.x] = 0.f;
    if (i < BB * OC_OFF * HW) {
        int oc = (i / HW) % OC_OFF;
        g_offset[i] = bias[oc];
    }
}

// ---------------- offset conv3x3: C in -> 18 out, pad 1 ----------------------
// Double-buffered halo tile: load cl+1 while computing cl (hides LDG latency).
#define CIN_CHUNK 64
__global__ __launch_bounds__(256) void offset_conv_kernel(
    const float* __restrict__ xin, const float* __restrict__ woff, int use_internal) {
    __shared__ __align__(16) float ws[CIN_CHUNK * 9 * 20];
    __shared__ float xs[2][18 * 18];

    int tid = threadIdx.x;
    int bz = blockIdx.z;
    int b = bz >> 2;
    int chunk = bz & 3;
    int cin0 = chunk * CIN_CHUNK;

    for (int idx = tid; idx < CIN_CHUNK * 9 * 18; idx += 256) {
        int cl = idx / 162;
        int rem = idx - cl * 162;
        int k = rem / 18;
        int oc = rem - k * 18;
        ws[(cl * 9 + k) * 20 + oc] =
            woff[(size_t)oc * (C * 9) + (size_t)(cin0 + cl) * 9 + k];
    }

    int ty = tid >> 4, tx = tid & 15;
    int py0 = blockIdx.y * 16, px0 = blockIdx.x * 16;

    float acc[18];
#pragma unroll
    for (int i = 0; i < 18; i++) acc[i] = 0.f;

    const float* src = use_internal ? g_act : xin;
    const float* xb = src + ((size_t)b * C + cin0) * HW;

    int hidx0 = tid;
    int hidx1 = tid + 256;
    int hr0 = hidx0 / 18, hc0 = hidx0 - hr0 * 18;
    int hr1 = hidx1 / 18, hc1 = hidx1 - hr1 * 18;
    int gy0 = py0 - 1 + hr0, gx0 = px0 - 1 + hc0;
    int gy1 = py0 - 1 + hr1, gx1 = px0 - 1 + hc1;
    bool v0 = (gy0 >= 0 && gy0 < H && gx0 >= 0 && gx0 < W);
    bool v1 = (hidx1 < 324) && (gy1 >= 0 && gy1 < H && gx1 >= 0 && gx1 < W);
    int go0 = gy0 * W + gx0, go1 = gy1 * W + gx1;

    {
        const float* xc = xb;
        xs[0][hidx0] = v0 ? xc[go0] : 0.f;
        if (hidx1 < 324) xs[0][hidx1] = v1 ? xc[go1] : 0.f;
    }
    __syncthreads();

#pragma unroll 1
    for (int cl = 0; cl < CIN_CHUNK; cl++) {
        int cur = cl & 1;
        if (cl + 1 < CIN_CHUNK) {
            const float* xn = xb + (size_t)(cl + 1) * HW;
            xs[cur ^ 1][hidx0] = v0 ? __ldg(xn + go0) : 0.f;
            if (hidx1 < 324) xs[cur ^ 1][hidx1] = v1 ? __ldg(xn + go1) : 0.f;
        }

        float xv[9];
#pragma unroll
        for (int ky = 0; ky < 3; ky++)
#pragma unroll
            for (int kx = 0; kx < 3; kx++)
                xv[ky * 3 + kx] = xs[cur][(ty + ky) * 18 + (tx + kx)];

#pragma unroll
        for (int k = 0; k < 9; k++) {
            const float* wr = &ws[(cl * 9 + k) * 20];
            float xk = xv[k];
#pragma unroll
            for (int oc = 0; oc < 18; oc++) acc[oc] += xk * wr[oc];
        }
        __syncthreads();
    }

    int p = (py0 + ty) * W + (px0 + tx);
    float* ob = g_offset + (size_t)b * OC_OFF * HW + p;
#pragma unroll
    for (int oc = 0; oc < 18; oc++) atomicAdd(ob + (size_t)oc * HW, acc[oc]);
}

// ---------------- bilinear gather -> val[b][p][k*256+cin] (fp16) -------------
// grid (16, 9, B*4): z = b*4 + channel chunk of 64. One thread per pixel.
__global__ __launch_bounds__(256) void gather_kernel(const float* __restrict__ xin,
                                                     int use_internal) {
    int tid = threadIdx.x;
    int p = blockIdx.x * 256 + tid;
    int k = blockIdx.y;
    int b = blockIdx.z >> 2;
    int cin0 = (blockIdx.z & 3) * 64;
    int h = p >> 6, w = p & 63;

    const float* off = g_offset + ((size_t)b * OC_OFF + 2 * k) * HW + p;
    float dy = off[0];
    float dx = off[HW];
    int ky = k / 3, kx = k - ky * 3;

    float py = dy + (float)(h - 1 + ky);
    float px = dx + (float)(w - 1 + kx);
    float fy = floorf(py), fx = floorf(px);
    int iy0 = (int)fy, ix0 = (int)fx;
    float ly = py - fy, lx = px - fx;

    float vy0 = (iy0 >= 0 && iy0 < H) ? 1.f : 0.f;
    float vy1 = (iy0 + 1 >= 0 && iy0 + 1 < H) ? 1.f : 0.f;
    float vx0 = (ix0 >= 0 && ix0 < W) ? 1.f : 0.f;
    float vx1 = (ix0 + 1 >= 0 && ix0 + 1 < W) ? 1.f : 0.f;

    float w00 = (1.f - ly) * (1.f - lx) * vy0 * vx0;
    float w01 = (1.f - ly) * lx * vy0 * vx1;
    float w10 = ly * (1.f - lx) * vy1 * vx0;
    float w11 = ly * lx * vy1 * vx1;

    int cy0 = min(max(iy0, 0), H - 1);
    int cy1 = min(max(iy0 + 1, 0), H - 1);
    int cx0 = min(max(ix0, 0), W - 1);
    int cx1 = min(max(ix0 + 1, 0), W - 1);
    int i00 = cy0 * W + cx0, i01 = cy0 * W + cx1;
    int i10 = cy1 * W + cx0, i11 = cy1 * W + cx1;

    const float* src = use_internal ? g_act : xin;
    const float* xb = src + (size_t)b * C * HW;
    __half* vo = g_val + ((size_t)b * HW + p) * CK + (size_t)k * 256;

#pragma unroll 1
    for (int c0 = cin0; c0 < cin0 + 64; c0 += 16) {
        const float* xc = xb + (size_t)c0 * HW;
        float v00[16], v01[16], v10[16], v11[16];
#pragma unroll
        for (int j = 0; j < 16; j++) v00[j] = __ldg(xc + (size_t)j * HW + i00);
#pragma unroll
        for (int j = 0; j < 16; j++) v01[j] = __ldg(xc + (size_t)j * HW + i01);
#pragma unroll
        for (int j = 0; j < 16; j++) v10[j] = __ldg(xc + (size_t)j * HW + i10);
#pragma unroll
        for (int j = 0; j < 16; j++) v11[j] = __ldg(xc + (size_t)j * HW + i11);

        __align__(16) __half hb[16];
#pragma unroll
        for (int j = 0; j < 16; j++) {
            float s = w00 * v00[j] + w01 * v01[j] + w10 * v10[j] + w11 * v11[j];
            hb[j] = __float2half(s);
        }
        *reinterpret_cast<uint4*>(vo + c0) = *reinterpret_cast<const uint4*>(hb);
        *reinterpret_cast<uint4*>(vo + c0 + 8) =
            *reinterpret_cast<const uint4*>(hb + 8);
    }
}

// ---------------- HMMA GEMM: D[p, oc] = sum_r val[p][r] * W[oc][r] -----------
// CTA tile 128(pixels) x 128(oc). fp16 2-term: A*Wh + A*Wl, fp32 accum.
// KC=64, 2-stage double buffer. Rows padded to 144B (conflict-free ldmatrix).
#define KC 64
#define NKC (CK / KC) /* 36 */
#define ROWB 144
#define A_OFF 0
#define BH_OFF (128 * ROWB)
#define BL_OFF (2 * 128 * ROWB)
#define STGSZ (3 * 128 * ROWB) /* 55296 */
#define GSMEM (2 * STGSZ)      /* 110592 */

__global__ __launch_bounds__(256, 2) void mma_gemm_kernel(int stage) {
    extern __shared__ __align__(16) char smem[];
    uint32_t sb = smem_u32(smem);
    int tid = threadIdx.x;
    int wid = tid >> 5, lane = tid & 31;
    int b = blockIdx.z;
    int n0 = blockIdx.y * 128;
    int p0 = blockIdx.x * 128;

    const __half* Ag = g_val + ((size_t)b * HW + p0) * CK;
    const __half* Bh = g_wh + ((size_t)stage * C + n0) * CK;
    const __half* Bl = g_wl + ((size_t)stage * C + n0) * CK;

    int arow = tid >> 1;
    int aseg = tid & 1;
    size_t agoff = (size_t)arow * CK + aseg * 32;
    uint32_t asoff = (uint32_t)arow * ROWB + (uint32_t)aseg * 64;
    int bplane = tid >> 7;
    int brow = tid & 127;
    const __half* Bg = (bplane ? Bl : Bh) + (size_t)brow * CK;
    uint32_t bsoff = (bplane ? BL_OFF : BH_OFF) + (uint32_t)brow * ROWB;

    int mwarp = wid >> 2, nwarp = wid & 3;
    uint32_t aoff = (uint32_t)(mwarp * 64 + (lane & 15)) * ROWB + (lane >> 4) * 16;
    uint32_t boff = (uint32_t)(nwarp * 32 + (lane >> 4) * 8 + (lane & 7)) * ROWB +
                    ((lane >> 3) & 1) * 16;

    float acc[4][4][4];
#pragma unroll
    for (int i = 0; i < 4; i++)
#pragma unroll
        for (int j = 0; j < 4; j++)
#pragma unroll
            for (int q = 0; q < 4; q++) acc[i][j][q] = 0.f;

#pragma unroll
    for (int s = 0; s < 2; s++) {
        uint32_t stb = sb + (uint32_t)s * STGSZ;
        int kc = s * KC;
#pragma unroll
        for (int j = 0; j < 4; j++)
            cp16(stb + A_OFF + asoff + j * 16, Ag + agoff + kc + j * 8);
#pragma unroll
        for (int j = 0; j < 8; j++)
            cp16(stb + bsoff + j * 16, Bg + kc + j * 8);
        asm volatile("cp.async.commit_group;" ::: "memory");
    }

#pragma unroll 1
    for (int i = 0; i < NKC; i++) {
        asm volatile("cp.async.wait_group 1;" ::: "memory");
        __syncthreads();

        uint32_t cb = sb + (uint32_t)(i & 1) * STGSZ;
#pragma unroll
        for (int kk = 0; kk < 4; kk++) {
            uint32_t koff = (uint32_t)kk * 32;
            uint32_t ah[4][4], bbh[2][4], bbl[2][4];
#pragma unroll
            for (int mt = 0; mt < 4; mt++)
                LDSM_X4(ah[mt], cb + A_OFF + aoff + (uint32_t)(mt * 16) * ROWB + koff);
#pragma unroll
            for (int ntp = 0; ntp < 2; ntp++)
                LDSM_X4(bbh[ntp],
                        cb + BH_OFF + boff + (uint32_t)(ntp * 16) * ROWB + koff);
#pragma unroll
            for (int mt = 0; mt < 4; mt++)
#pragma unroll
                for (int nt = 0; nt < 4; nt++)
                    MMA_F16(acc[mt][nt], ah[mt], &bbh[nt >> 1][(nt & 1) * 2]);
#pragma unroll
            for (int ntp = 0; ntp < 2; ntp++)
                LDSM_X4(bbl[ntp],
                        cb + BL_OFF + boff + (uint32_t)(ntp * 16) * ROWB + koff);
#pragma unroll
            for (int mt = 0; mt < 4; mt++)
#pragma unroll
                for (int nt = 0; nt < 4; nt++)
                    MMA_F16(acc[mt][nt], ah[mt], &bbl[nt >> 1][(nt & 1) * 2]);
        }
        __syncthreads();

        if (i + 2 < NKC) {
            uint32_t stb = sb + (uint32_t)(i & 1) * STGSZ;
            int kc = (i + 2) * KC;
#pragma unroll
            for (int j = 0; j < 4; j++)
                cp16(stb + A_OFF + asoff + j * 16, Ag + agoff + kc + j * 8);
#pragma unroll
            for (int j = 0; j < 8; j++)
                cp16(stb + bsoff + j * 16, Bg + kc + j * 8);
        }
        asm volatile("cp.async.commit_group;" ::: "memory");
    }
    __syncthreads();

    // ---------------- epilogue: smem transpose [n][m], stores + GN stats -----
    float* sf = reinterpret_cast<float*>(smem);
    int rl = lane >> 2;
    int cl2 = (lane & 3) * 2;
#pragma unroll
    for (int mt = 0; mt < 4; mt++) {
#pragma unroll
        for (int nt = 0; nt < 4; nt++) {
            int m = mwarp * 64 + mt * 16 + rl;
            int n = nwarp * 32 + nt * 8 + cl2;
            sf[n * 132 + m] = acc[mt][nt][0];
            sf[(n + 1) * 132 + m] = acc[mt][nt][1];
            sf[n * 132 + m + 8] = acc[mt][nt][2];
            sf[(n + 1) * 132 + m + 8] = acc[mt][nt][3];
        }
    }
    __syncthreads();

    float* Cp = g_tmp + ((size_t)b * C + n0) * HW + p0;
#pragma unroll
    for (int t = 0; t < 16; t++) {
        int idx = tid + t * 256;
        int n = idx >> 5;
        int ms = (idx & 31) * 4;
        float4 v = *reinterpret_cast<const float4*>(sf + n * 132 + ms);
        *reinterpret_cast<float4*>(Cp + (size_t)n * HW + ms) = v;

        float s1 = v.x + v.y + v.z + v.w;
        float s2 = v.x * v.x + v.y * v.y + v.z * v.z + v.w * v.w;
#pragma unroll
        for (int o = 16; o > 0; o >>= 1) {
            s1 += __shfl_xor_sync(0xffffffffu, s1, o);
            s2 += __shfl_xor_sync(0xffffffffu, s2, o);
        }
        if (lane == 0) {
            int bg = b * G + ((n0 + n) >> 3);
            atomicAdd(&g_stat[bg * 2], s1);
            atomicAdd(&g_stat[bg * 2 + 1], s2);
        }
    }
}

// ---------------- GroupNorm apply (+ReLU, optional residual) -----------------
// grid (BB*G, 4): each CTA handles 2 of the group's 8 channels.
__global__ __launch_bounds__(256) void gn_kernel(const float* __restrict__ gamma,
                                                 const float* __restrict__ beta,
                                                 const float* __restrict__ residual,
                                                 float* __restrict__ outp,
                                                 int use_internal) {
    int bg = blockIdx.x;
    int b = bg >> 5;
    int g = bg & 31;
    int quarter = blockIdx.y;
    size_t chan_off = ((size_t)b * C + (size_t)g * 8 + (size_t)quarter * 2) * HW;
    const float4* in4 = reinterpret_cast<const float4*>(g_tmp + chan_off);

    __shared__ float stats[2];
    if (threadIdx.x == 0) {
        float inv_n = 1.f / 32768.f;
        float mu = g_stat[bg * 2] * inv_n;
        stats[0] = mu;
        stats[1] = rsqrtf(g_stat[bg * 2 + 1] * inv_n - mu * mu + 1e-5f);
    }
    __syncthreads();
    float mu = stats[0], rstd = stats[1];

    int tid = threadIdx.x;
    float* dst = (use_internal ? g_act : outp) + chan_off;
    float4* out4 = reinterpret_cast<float4*>(dst);
    const float4* res4 =
        residual ? reinterpret_cast<const float4*>(residual + chan_off) : nullptr;

    for (int i = tid; i < 2 * HW / 4; i += 256) {
        int c = g * 8 + quarter * 2 + (i >> 10);
        float gm = gamma[c] * rstd;
        float bt = beta[c] - mu * gm;
        float4 v = in4[i];
        v.x = v.x * gm + bt;
        v.y = v.y * gm + bt;
        v.z = v.z * gm + bt;
        v.w = v.w * gm + bt;
        if (res4) {
            float4 r = res4[i];
            v.x += r.x; v.y += r.y; v.z += r.z; v.w += r.w;
        }
        v.x = fmaxf(v.x, 0.f);
        v.y = fmaxf(v.y, 0.f);
        v.z = fmaxf(v.z, 0.f);
        v.w = fmaxf(v.w, 0.f);
        out4[i] = v;
    }
}

// ---------------- launcher ---------------------------------------------------
extern "C" void kernel_launch(void* const* d_in, const int* in_sizes, int n_in,
                              void* d_out, int out_size) {
    const float* x      = (const float*)d_in[0];
    const float* w_off1 = (const float*)d_in[1];
    const float* b_off1 = (const float*)d_in[2];
    const float* w_off2 = (const float*)d_in[3];
    const float* b_off2 = (const float*)d_in[4];
    const float* w_def1 = (const float*)d_in[5];
    const float* w_def2 = (const float*)d_in[6];
    const float* gamma1 = (const float*)d_in[7];
    const float* beta1  = (const float*)d_in[8];
    const float* gamma2 = (const float*)d_in[9];
    const float* beta2  = (const float*)d_in[10];
    float* out = (float*)d_out;

    cudaFuncSetAttribute(mma_gemm_kernel, cudaFuncAttributeMaxDynamicSharedMemorySize,
                         GSMEM);

    dim3 conv_grid(4, 4, BB * 4);
    dim3 gath_grid(HW / 256, KK, BB * 4);
    dim3 gemm_grid(HW / 128, C / 128, BB);
    dim3 gn_grid(BB * G, 4);
    int init_blocks = (BB * OC_OFF * HW + 255) / 256;
    int wprep_blocks = (2 * C * CK + 255) / 256;  // covers init range too (294912>294912? yes: 2*C*CK=1,179,648 > BB*OC_OFF*HW=294,912)

    // ---- stage 1 (stage-1 offset init folded into wprep) ----
    wprep_kernel<<<wprep_blocks, 256>>>(w_def1, w_def2, b_off1);
    offset_conv_kernel<<<conv_grid, 256>>>(x, w_off1, 0);
    gather_kernel<<<gath_grid, 256>>>(x, 0);
    mma_gemm_kernel<<<gemm_grid, 256, GSMEM>>>(0);
    gn_kernel<<<gn_grid, 256>>>(gamma1, beta1, nullptr, nullptr, 1);

    // ---- stage 2 ----
    init_offset_kernel<<<init_blocks, 256>>>(b_off2);
    offset_conv_kernel<<<conv_grid, 256>>>(nullptr, w_off2, 1);
    gather_kernel<<<gath_grid, 256>>>(nullptr, 1);
    mma_gemm_kernel<<<gemm_grid, 256, GSMEM>>>(1);
    gn_kernel<<<gn_grid, 256>>>(gamma2, beta2, x, out, 0);
}

// round 11
// speedup vs baseline: 1.7979x; 1.2427x over previous
#include <cuda_runtime.h>
#include <cuda_fp16.h>
#include <cstdint>

#define BB 4
#define C 256
#define H 64
#define W 64
#define HW 4096
#define G 32
#define KK 9
#define OC_OFF 18
#define CK 2304  /* C * KK */

// ---------------- device scratch (static, no runtime allocation) -------------
__device__ float g_offset[BB * OC_OFF * HW];                      // 1.18 MB
__device__ __align__(16) __half g_val[(size_t)BB * HW * CK];      // 75.5 MB
__device__ __align__(16) __half g_wh[2 * C * CK];                 // 2.36 MB
__device__ float g_tmp[(size_t)BB * C * HW];                      // 16.8 MB
__device__ float g_act[(size_t)BB * C * HW];                      // 16.8 MB
__device__ float g_stat[BB * G * 2];                              // group sums

// ---------------- helpers ----------------------------------------------------
__device__ __forceinline__ uint32_t smem_u32(const void* p) {
    uint32_t a;
    asm("{ .reg .u64 t; cvta.to.shared.u64 t, %1; cvt.u32.u64 %0, t; }"
        : "=r"(a) : "l"(p));
    return a;
}
__device__ __forceinline__ void cp16(uint32_t saddr, const void* gaddr) {
    asm volatile("cp.async.cg.shared.global [%0], [%1], 16;"
                 :: "r"(saddr), "l"(gaddr));
}

#define MMA_F16(d, a, bfr)                                                   \
    asm volatile(                                                            \
        "mma.sync.aligned.m16n8k16.row.col.f32.f16.f16.f32 "                 \
        "{%0,%1,%2,%3}, {%4,%5,%6,%7}, {%8,%9}, {%0,%1,%2,%3};"              \
        : "+f"((d)[0]), "+f"((d)[1]), "+f"((d)[2]), "+f"((d)[3])             \
        : "r"((a)[0]), "r"((a)[1]), "r"((a)[2]), "r"((a)[3]),                \
          "r"((bfr)[0]), "r"((bfr)[1]))

#define LDSM_X4(fr, addr)                                                    \
    asm volatile("ldmatrix.sync.aligned.m8n8.x4.shared.b16 "                 \
                 "{%0,%1,%2,%3}, [%4];"                                      \
                 : "=r"((fr)[0]), "=r"((fr)[1]), "=r"((fr)[2]), "=r"((fr)[3])\
                 : "r"(addr))

// ---------------- weight reorder + stage-1 offset init -----------------------
// w[oc][cin][k] -> fp16 [oc][k*256+cin]; also seeds g_offset with b_off1 and
// clears g_stat (folded stage-1 init to drop one launch).
__global__ void wprep_kernel(const float* __restrict__ w1, const float* __restrict__ w2,
                             const float* __restrict__ bias1) {
    int i = blockIdx.x * 256 + threadIdx.x;
    if (blockIdx.x == 0 && threadIdx.x < BB * G * 2) g_stat[threadIdx.x] = 0.f;
    if (i < BB * OC_OFF * HW) {
        int oc = (i / HW) % OC_OFF;
        g_offset[i] = bias1[oc];
    }
    if (i >= 2 * C * CK) return;
    int s = i / (C * CK);
    int rem = i - s * (C * CK);
    int oc = rem / CK;
    int r = rem - oc * CK;
    int k = r >> 8;
    int cin = r & 255;
    const float* w = s ? w2 : w1;
    g_wh[i] = __float2half(w[(size_t)oc * CK + cin * 9 + k]);
}

// ---------------- init offset buffer with bias + clear group stats -----------
__global__ void init_offset_kernel(const float* __restrict__ bias) {
    int i = blockIdx.x * 256 + threadIdx.x;
    if (blockIdx.x == 0 && threadIdx.x < BB * G * 2) g_stat[threadIdx.x] = 0.f;
    if (i < BB * OC_OFF * HW) {
        int oc = (i / HW) % OC_OFF;
        g_offset[i] = bias[oc];
    }
}

// ---------------- offset conv3x3: C in -> 18 out, pad 1 ----------------------
// Double-buffered halo tile: load cl+1 while computing cl (hides LDG latency).
#define CIN_CHUNK 64
__global__ __launch_bounds__(256) void offset_conv_kernel(
    const float* __restrict__ xin, const float* __restrict__ woff, int use_internal) {
    __shared__ __align__(16) float ws[CIN_CHUNK * 9 * 20];
    __shared__ float xs[2][18 * 18];

    int tid = threadIdx.x;
    int bz = blockIdx.z;
    int b = bz >> 2;
    int chunk = bz & 3;
    int cin0 = chunk * CIN_CHUNK;

    for (int idx = tid; idx < CIN_CHUNK * 9 * 18; idx += 256) {
        int cl = idx / 162;
        int rem = idx - cl * 162;
        int k = rem / 18;
        int oc = rem - k * 18;
        ws[(cl * 9 + k) * 20 + oc] =
            woff[(size_t)oc * (C * 9) + (size_t)(cin0 + cl) * 9 + k];
    }

    int ty = tid >> 4, tx = tid & 15;
    int py0 = blockIdx.y * 16, px0 = blockIdx.x * 16;

    float acc[18];
#pragma unroll
    for (int i = 0; i < 18; i++) acc[i] = 0.f;

    const float* src = use_internal ? g_act : xin;
    const float* xb = src + ((size_t)b * C + cin0) * HW;

    int hidx0 = tid;
    int hidx1 = tid + 256;
    int hr0 = hidx0 / 18, hc0 = hidx0 - hr0 * 18;
    int hr1 = hidx1 / 18, hc1 = hidx1 - hr1 * 18;
    int gy0 = py0 - 1 + hr0, gx0 = px0 - 1 + hc0;
    int gy1 = py0 - 1 + hr1, gx1 = px0 - 1 + hc1;
    bool v0 = (gy0 >= 0 && gy0 < H && gx0 >= 0 && gx0 < W);
    bool v1 = (hidx1 < 324) && (gy1 >= 0 && gy1 < H && gx1 >= 0 && gx1 < W);
    int go0 = gy0 * W + gx0, go1 = gy1 * W + gx1;

    {
        const float* xc = xb;
        xs[0][hidx0] = v0 ? xc[go0] : 0.f;
        if (hidx1 < 324) xs[0][hidx1] = v1 ? xc[go1] : 0.f;
    }
    __syncthreads();

#pragma unroll 1
    for (int cl = 0; cl < CIN_CHUNK; cl++) {
        int cur = cl & 1;
        if (cl + 1 < CIN_CHUNK) {
            const float* xn = xb + (size_t)(cl + 1) * HW;
            xs[cur ^ 1][hidx0] = v0 ? __ldg(xn + go0) : 0.f;
            if (hidx1 < 324) xs[cur ^ 1][hidx1] = v1 ? __ldg(xn + go1) : 0.f;
        }

        float xv[9];
#pragma unroll
        for (int ky = 0; ky < 3; ky++)
#pragma unroll
            for (int kx = 0; kx < 3; kx++)
                xv[ky * 3 + kx] = xs[cur][(ty + ky) * 18 + (tx + kx)];

#pragma unroll
        for (int k = 0; k < 9; k++) {
            const float* wr = &ws[(cl * 9 + k) * 20];
            float xk = xv[k];
#pragma unroll
            for (int oc = 0; oc < 18; oc++) acc[oc] += xk * wr[oc];
        }
        __syncthreads();
    }

    int p = (py0 + ty) * W + (px0 + tx);
    float* ob = g_offset + (size_t)b * OC_OFF * HW + p;
#pragma unroll
    for (int oc = 0; oc < 18; oc++) atomicAdd(ob + (size_t)oc * HW, acc[oc]);
}

// ---------------- bilinear gather -> val[b][p][k*256+cin] (fp16) -------------
// grid (16, 9, B*4): z = b*4 + channel chunk of 64. One thread per pixel.
__global__ __launch_bounds__(256) void gather_kernel(const float* __restrict__ xin,
                                                     int use_internal) {
    int tid = threadIdx.x;
    int p = blockIdx.x * 256 + tid;
    int k = blockIdx.y;
    int b = blockIdx.z >> 2;
    int cin0 = (blockIdx.z & 3) * 64;
    int h = p >> 6, w = p & 63;

    const float* off = g_offset + ((size_t)b * OC_OFF + 2 * k) * HW + p;
    float dy = off[0];
    float dx = off[HW];
    int ky = k / 3, kx = k - ky * 3;

    float py = dy + (float)(h - 1 + ky);
    float px = dx + (float)(w - 1 + kx);
    float fy = floorf(py), fx = floorf(px);
    int iy0 = (int)fy, ix0 = (int)fx;
    float ly = py - fy, lx = px - fx;

    float vy0 = (iy0 >= 0 && iy0 < H) ? 1.f : 0.f;
    float vy1 = (iy0 + 1 >= 0 && iy0 + 1 < H) ? 1.f : 0.f;
    float vx0 = (ix0 >= 0 && ix0 < W) ? 1.f : 0.f;
    float vx1 = (ix0 + 1 >= 0 && ix0 + 1 < W) ? 1.f : 0.f;

    float w00 = (1.f - ly) * (1.f - lx) * vy0 * vx0;
    float w01 = (1.f - ly) * lx * vy0 * vx1;
    float w10 = ly * (1.f - lx) * vy1 * vx0;
    float w11 = ly * lx * vy1 * vx1;

    int cy0 = min(max(iy0, 0), H - 1);
    int cy1 = min(max(iy0 + 1, 0), H - 1);
    int cx0 = min(max(ix0, 0), W - 1);
    int cx1 = min(max(ix0 + 1, 0), W - 1);
    int i00 = cy0 * W + cx0, i01 = cy0 * W + cx1;
    int i10 = cy1 * W + cx0, i11 = cy1 * W + cx1;

    const float* src = use_internal ? g_act : xin;
    const float* xb = src + (size_t)b * C * HW;
    __half* vo = g_val + ((size_t)b * HW + p) * CK + (size_t)k * 256;

#pragma unroll 1
    for (int c0 = cin0; c0 < cin0 + 64; c0 += 16) {
        const float* xc = xb + (size_t)c0 * HW;
        float v00[16], v01[16], v10[16], v11[16];
#pragma unroll
        for (int j = 0; j < 16; j++) v00[j] = __ldg(xc + (size_t)j * HW + i00);
#pragma unroll
        for (int j = 0; j < 16; j++) v01[j] = __ldg(xc + (size_t)j * HW + i01);
#pragma unroll
        for (int j = 0; j < 16; j++) v10[j] = __ldg(xc + (size_t)j * HW + i10);
#pragma unroll
        for (int j = 0; j < 16; j++) v11[j] = __ldg(xc + (size_t)j * HW + i11);

        __align__(16) __half hb[16];
#pragma unroll
        for (int j = 0; j < 16; j++) {
            float s = w00 * v00[j] + w01 * v01[j] + w10 * v10[j] + w11 * v11[j];
            hb[j] = __float2half(s);
        }
        *reinterpret_cast<uint4*>(vo + c0) = *reinterpret_cast<const uint4*>(hb);
        *reinterpret_cast<uint4*>(vo + c0 + 8) =
            *reinterpret_cast<const uint4*>(hb + 8);
    }
}

// ---------------- HMMA GEMM: D[p, oc] = sum_r val[p][r] * W[oc][r] -----------
// CTA tile 128(pixels) x 128(oc). Plain fp16 x fp16, fp32 accum.
// KC=64, 2-stage double buffer. Rows padded to 144B (conflict-free ldmatrix).
#define KC 64
#define NKC (CK / KC) /* 36 */
#define ROWB 144
#define A_OFF 0
#define B_OFF (128 * ROWB)
#define STGSZ (2 * 128 * ROWB) /* 36864 */
#define GSMEM (2 * STGSZ)      /* 73728 */

__global__ __launch_bounds__(256, 2) void mma_gemm_kernel(int stage) {
    extern __shared__ __align__(16) char smem[];
    uint32_t sb = smem_u32(smem);
    int tid = threadIdx.x;
    int wid = tid >> 5, lane = tid & 31;
    int b = blockIdx.z;
    int n0 = blockIdx.y * 128;
    int p0 = blockIdx.x * 128;

    const __half* Ag = g_val + ((size_t)b * HW + p0) * CK;
    const __half* Bg = g_wh + ((size_t)stage * C + n0) * CK;

    // loads: 2 threads/row, 64B (4x16B) each, for both A and B tiles.
    int lrow = tid >> 1;
    int lseg = tid & 1;
    size_t goff = (size_t)lrow * CK + lseg * 32;
    uint32_t soff = (uint32_t)lrow * ROWB + (uint32_t)lseg * 64;

    int mwarp = wid >> 2, nwarp = wid & 3;
    uint32_t aoff = (uint32_t)(mwarp * 64 + (lane & 15)) * ROWB + (lane >> 4) * 16;
    uint32_t boff = (uint32_t)(nwarp * 32 + (lane >> 4) * 8 + (lane & 7)) * ROWB +
                    ((lane >> 3) & 1) * 16;

    float acc[4][4][4];
#pragma unroll
    for (int i = 0; i < 4; i++)
#pragma unroll
        for (int j = 0; j < 4; j++)
#pragma unroll
            for (int q = 0; q < 4; q++) acc[i][j][q] = 0.f;

#pragma unroll
    for (int s = 0; s < 2; s++) {
        uint32_t stb = sb + (uint32_t)s * STGSZ;
        int kc = s * KC;
#pragma unroll
        for (int j = 0; j < 4; j++) {
            cp16(stb + A_OFF + soff + j * 16, Ag + goff + kc + j * 8);
            cp16(stb + B_OFF + soff + j * 16, Bg + goff + kc + j * 8);
        }
        asm volatile("cp.async.commit_group;" ::: "memory");
    }

#pragma unroll 1
    for (int i = 0; i < NKC; i++) {
        asm volatile("cp.async.wait_group 1;" ::: "memory");
        __syncthreads();

        uint32_t cb = sb + (uint32_t)(i & 1) * STGSZ;
#pragma unroll
        for (int kk = 0; kk < 4; kk++) {
            uint32_t koff = (uint32_t)kk * 32;
            uint32_t ah[4][4], bb[2][4];
#pragma unroll
            for (int mt = 0; mt < 4; mt++)
                LDSM_X4(ah[mt], cb + A_OFF + aoff + (uint32_t)(mt * 16) * ROWB + koff);
#pragma unroll
            for (int ntp = 0; ntp < 2; ntp++)
                LDSM_X4(bb[ntp],
                        cb + B_OFF + boff + (uint32_t)(ntp * 16) * ROWB + koff);
#pragma unroll
            for (int mt = 0; mt < 4; mt++)
#pragma unroll
                for (int nt = 0; nt < 4; nt++)
                    MMA_F16(acc[mt][nt], ah[mt], &bb[nt >> 1][(nt & 1) * 2]);
        }
        __syncthreads();

        if (i + 2 < NKC) {
            uint32_t stb = sb + (uint32_t)(i & 1) * STGSZ;
            int kc = (i + 2) * KC;
#pragma unroll
            for (int j = 0; j < 4; j++) {
                cp16(stb + A_OFF + soff + j * 16, Ag + goff + kc + j * 8);
                cp16(stb + B_OFF + soff + j * 16, Bg + goff + kc + j * 8);
            }
        }
        asm volatile("cp.async.commit_group;" ::: "memory");
    }
    __syncthreads();

    // ---------------- epilogue: smem transpose [n][m], stores + GN stats -----
    float* sf = reinterpret_cast<float*>(smem);
    int rl = lane >> 2;
    int cl2 = (lane & 3) * 2;
#pragma unroll
    for (int mt = 0; mt < 4; mt++) {
#pragma unroll
        for (int nt = 0; nt < 4; nt++) {
            int m = mwarp * 64 + mt * 16 + rl;
            int n = nwarp * 32 + nt * 8 + cl2;
            sf[n * 132 + m] = acc[mt][nt][0];
            sf[(n + 1) * 132 + m] = acc[mt][nt][1];
            sf[n * 132 + m + 8] = acc[mt][nt][2];
            sf[(n + 1) * 132 + m + 8] = acc[mt][nt][3];
        }
    }
    __syncthreads();

    float* Cp = g_tmp + ((size_t)b * C + n0) * HW + p0;
#pragma unroll
    for (int t = 0; t < 16; t++) {
        int idx = tid + t * 256;
        int n = idx >> 5;
        int ms = (idx & 31) * 4;
        float4 v = *reinterpret_cast<const float4*>(sf + n * 132 + ms);
        *reinterpret_cast<float4*>(Cp + (size_t)n * HW + ms) = v;

        float s1 = v.x + v.y + v.z + v.w;
        float s2 = v.x * v.x + v.y * v.y + v.z * v.z + v.w * v.w;
#pragma unroll
        for (int o = 16; o > 0; o >>= 1) {
            s1 += __shfl_xor_sync(0xffffffffu, s1, o);
            s2 += __shfl_xor_sync(0xffffffffu, s2, o);
        }
        if (lane == 0) {
            int bg = b * G + ((n0 + n) >> 3);
            atomicAdd(&g_stat[bg * 2], s1);
            atomicAdd(&g_stat[bg * 2 + 1], s2);
        }
    }
}

// ---------------- GroupNorm apply (+ReLU, optional residual) -----------------
// grid (BB*G, 4): each CTA handles 2 of the group's 8 channels.
__global__ __launch_bounds__(256) void gn_kernel(const float* __restrict__ gamma,
                                                 const float* __restrict__ beta,
                                                 const float* __restrict__ residual,
                                                 float* __restrict__ outp,
                                                 int use_internal) {
    int bg = blockIdx.x;
    int b = bg >> 5;
    int g = bg & 31;
    int quarter = blockIdx.y;
    size_t chan_off = ((size_t)b * C + (size_t)g * 8 + (size_t)quarter * 2) * HW;
    const float4* in4 = reinterpret_cast<const float4*>(g_tmp + chan_off);

    __shared__ float stats[2];
    if (threadIdx.x == 0) {
        float inv_n = 1.f / 32768.f;
        float mu = g_stat[bg * 2] * inv_n;
        stats[0] = mu;
        stats[1] = rsqrtf(g_stat[bg * 2 + 1] * inv_n - mu * mu + 1e-5f);
    }
    __syncthreads();
    float mu = stats[0], rstd = stats[1];

    int tid = threadIdx.x;
    float* dst = (use_internal ? g_act : outp) + chan_off;
    float4* out4 = reinterpret_cast<float4*>(dst);
    const float4* res4 =
        residual ? reinterpret_cast<const float4*>(residual + chan_off) : nullptr;

    for (int i = tid; i < 2 * HW / 4; i += 256) {
        int c = g * 8 + quarter * 2 + (i >> 10);
        float gm = gamma[c] * rstd;
        float bt = beta[c] - mu * gm;
        float4 v = in4[i];
        v.x = v.x * gm + bt;
        v.y = v.y * gm + bt;
        v.z = v.z * gm + bt;
        v.w = v.w * gm + bt;
        if (res4) {
            float4 r = res4[i];
            v.x += r.x; v.y += r.y; v.z += r.z; v.w += r.w;
        }
        v.x = fmaxf(v.x, 0.f);
        v.y = fmaxf(v.y, 0.f);
        v.z = fmaxf(v.z, 0.f);
        v.w = fmaxf(v.w, 0.f);
        out4[i] = v;
    }
}

// ---------------- launcher ---------------------------------------------------
extern "C" void kernel_launch(void* const* d_in, const int* in_sizes, int n_in,
                              void* d_out, int out_size) {
    const float* x      = (const float*)d_in[0];
    const float* w_off1 = (const float*)d_in[1];
    const float* b_off1 = (const float*)d_in[2];
    const float* w_off2 = (const float*)d_in[3];
    const float* b_off2 = (const float*)d_in[4];
    const float* w_def1 = (const float*)d_in[5];
    const float* w_def2 = (const float*)d_in[6];
    const float* gamma1 = (const float*)d_in[7];
    const float* beta1  = (const float*)d_in[8];
    const float* gamma2 = (const float*)d_in[9];
    const float* beta2  = (const float*)d_in[10];
    float* out = (float*)d_out;

    cudaFuncSetAttribute(mma_gemm_kernel, cudaFuncAttributeMaxDynamicSharedMemorySize,
                         GSMEM);

    dim3 conv_grid(4, 4, BB * 4);
    dim3 gath_grid(HW / 256, KK, BB * 4);
    dim3 gemm_grid(HW / 128, C / 128, BB);
    dim3 gn_grid(BB * G, 4);
    int init_blocks = (BB * OC_OFF * HW + 255) / 256;
    int wprep_blocks = (2 * C * CK + 255) / 256;  // covers g_offset init range too

    // ---- stage 1 (stage-1 offset init folded into wprep) ----
    wprep_kernel<<<wprep_blocks, 256>>>(w_def1, w_def2, b_off1);
    offset_conv_kernel<<<conv_grid, 256>>>(x, w_off1, 0);
    gather_kernel<<<gath_grid, 256>>>(x, 0);
    mma_gemm_kernel<<<gemm_grid, 256, GSMEM>>>(0);
    gn_kernel<<<gn_grid, 256>>>(gamma1, beta1, nullptr, nullptr, 1);

    // ---- stage 2 ----
    init_offset_kernel<<<init_blocks, 256>>>(b_off2);
    offset_conv_kernel<<<conv_grid, 256>>>(nullptr, w_off2, 1);
    gather_kernel<<<gath_grid, 256>>>(nullptr, 1);
    mma_gemm_kernel<<<gemm_grid, 256, GSMEM>>>(1);
    gn_kernel<<<gn_grid, 256>>>(gamma2, beta2, x, out, 0);
}

// round 12
// speedup vs baseline: 1.8766x; 1.0438x over previous
#include <cuda_runtime.h>
#include <cuda_fp16.h>
#include <cstdint>

#define BB 4
#define C 256
#define H 64
#define W 64
#define HW 4096
#define G 32
#define KK 9
#define OC_OFF 18
#define CK 2304  /* C * KK */

// ---------------- device scratch (static, no runtime allocation) -------------
__device__ float g_offset[BB * OC_OFF * HW];                      // 1.18 MB
__device__ __align__(16) __half g_val[(size_t)BB * HW * CK];      // 75.5 MB
__device__ __align__(16) __half g_wh[2 * C * CK];                 // 2.36 MB
__device__ float g_tmp[(size_t)BB * C * HW];                      // 16.8 MB
__device__ float g_act[(size_t)BB * C * HW];                      // 16.8 MB
__device__ float g_stat[BB * G * 2];                              // group sums

// ---------------- helpers ----------------------------------------------------
__device__ __forceinline__ uint32_t smem_u32(const void* p) {
    uint32_t a;
    asm("{ .reg .u64 t; cvta.to.shared.u64 t, %1; cvt.u32.u64 %0, t; }"
        : "=r"(a) : "l"(p));
    return a;
}
__device__ __forceinline__ void cp16(uint32_t saddr, const void* gaddr) {
    asm volatile("cp.async.cg.shared.global [%0], [%1], 16;"
                 :: "r"(saddr), "l"(gaddr));
}

#define MMA_F16(d, a, bfr)                                                   \
    asm volatile(                                                            \
        "mma.sync.aligned.m16n8k16.row.col.f32.f16.f16.f32 "                 \
        "{%0,%1,%2,%3}, {%4,%5,%6,%7}, {%8,%9}, {%0,%1,%2,%3};"              \
        : "+f"((d)[0]), "+f"((d)[1]), "+f"((d)[2]), "+f"((d)[3])             \
        : "r"((a)[0]), "r"((a)[1]), "r"((a)[2]), "r"((a)[3]),                \
          "r"((bfr)[0]), "r"((bfr)[1]))

#define LDSM_X4(fr, addr)                                                    \
    asm volatile("ldmatrix.sync.aligned.m8n8.x4.shared.b16 "                 \
                 "{%0,%1,%2,%3}, [%4];"                                      \
                 : "=r"((fr)[0]), "=r"((fr)[1]), "=r"((fr)[2]), "=r"((fr)[3])\
                 : "r"(addr))

// ---------------- weight reorder + stage-1 offset init -----------------------
__global__ void wprep_kernel(const float* __restrict__ w1, const float* __restrict__ w2,
                             const float* __restrict__ bias1) {
    int i = blockIdx.x * 256 + threadIdx.x;
    if (blockIdx.x == 0 && threadIdx.x < BB * G * 2) g_stat[threadIdx.x] = 0.f;
    if (i < BB * OC_OFF * HW) {
        int oc = (i / HW) % OC_OFF;
        g_offset[i] = bias1[oc];
    }
    if (i >= 2 * C * CK) return;
    int s = i / (C * CK);
    int rem = i - s * (C * CK);
    int oc = rem / CK;
    int r = rem - oc * CK;
    int k = r >> 8;
    int cin = r & 255;
    const float* w = s ? w2 : w1;
    g_wh[i] = __float2half(w[(size_t)oc * CK + cin * 9 + k]);
}

// ---------------- init offset buffer with bias + clear group stats -----------
__global__ void init_offset_kernel(const float* __restrict__ bias) {
    int i = blockIdx.x * 256 + threadIdx.x;
    if (blockIdx.x == 0 && threadIdx.x < BB * G * 2) g_stat[threadIdx.x] = 0.f;
    if (i < BB * OC_OFF * HW) {
        int oc = (i / HW) % OC_OFF;
        g_offset[i] = bias[oc];
    }
}

// ---------------- offset conv3x3: C in -> 18 out, pad 1 ----------------------
#define CIN_CHUNK 64
__global__ __launch_bounds__(256) void offset_conv_kernel(
    const float* __restrict__ xin, const float* __restrict__ woff, int use_internal) {
    __shared__ __align__(16) float ws[CIN_CHUNK * 9 * 20];
    __shared__ float xs[2][18 * 18];

    int tid = threadIdx.x;
    int bz = blockIdx.z;
    int b = bz >> 2;
    int chunk = bz & 3;
    int cin0 = chunk * CIN_CHUNK;

    for (int idx = tid; idx < CIN_CHUNK * 9 * 18; idx += 256) {
        int cl = idx / 162;
        int rem = idx - cl * 162;
        int k = rem / 18;
        int oc = rem - k * 18;
        ws[(cl * 9 + k) * 20 + oc] =
            woff[(size_t)oc * (C * 9) + (size_t)(cin0 + cl) * 9 + k];
    }

    int ty = tid >> 4, tx = tid & 15;
    int py0 = blockIdx.y * 16, px0 = blockIdx.x * 16;

    float acc[18];
#pragma unroll
    for (int i = 0; i < 18; i++) acc[i] = 0.f;

    const float* src = use_internal ? g_act : xin;
    const float* xb = src + ((size_t)b * C + cin0) * HW;

    int hidx0 = tid;
    int hidx1 = tid + 256;
    int hr0 = hidx0 / 18, hc0 = hidx0 - hr0 * 18;
    int hr1 = hidx1 / 18, hc1 = hidx1 - hr1 * 18;
    int gy0 = py0 - 1 + hr0, gx0 = px0 - 1 + hc0;
    int gy1 = py0 - 1 + hr1, gx1 = px0 - 1 + hc1;
    bool v0 = (gy0 >= 0 && gy0 < H && gx0 >= 0 && gx0 < W);
    bool v1 = (hidx1 < 324) && (gy1 >= 0 && gy1 < H && gx1 >= 0 && gx1 < W);
    int go0 = gy0 * W + gx0, go1 = gy1 * W + gx1;

    {
        const float* xc = xb;
        xs[0][hidx0] = v0 ? xc[go0] : 0.f;
        if (hidx1 < 324) xs[0][hidx1] = v1 ? xc[go1] : 0.f;
    }
    __syncthreads();

#pragma unroll 1
    for (int cl = 0; cl < CIN_CHUNK; cl++) {
        int cur = cl & 1;
        if (cl + 1 < CIN_CHUNK) {
            const float* xn = xb + (size_t)(cl + 1) * HW;
            xs[cur ^ 1][hidx0] = v0 ? __ldg(xn + go0) : 0.f;
            if (hidx1 < 324) xs[cur ^ 1][hidx1] = v1 ? __ldg(xn + go1) : 0.f;
        }

        float xv[9];
#pragma unroll
        for (int ky = 0; ky < 3; ky++)
#pragma unroll
            for (int kx = 0; kx < 3; kx++)
                xv[ky * 3 + kx] = xs[cur][(ty + ky) * 18 + (tx + kx)];

#pragma unroll
        for (int k = 0; k < 9; k++) {
            const float* wr = &ws[(cl * 9 + k) * 20];
            float xk = xv[k];
#pragma unroll
            for (int oc = 0; oc < 18; oc++) acc[oc] += xk * wr[oc];
        }
        __syncthreads();
    }

    int p = (py0 + ty) * W + (px0 + tx);
    float* ob = g_offset + (size_t)b * OC_OFF * HW + p;
#pragma unroll
    for (int oc = 0; oc < 18; oc++) atomicAdd(ob + (size_t)oc * HW, acc[oc]);
}

// ---------------- bilinear gather -> val[b][p][k*256+cin] (fp16) -------------
// grid (16, 9, B*4). Compute into swizzled smem (conflict-free STS.128), then
// copy out with 8 threads/pixel -> 128B-line coalesced global stores.
__global__ __launch_bounds__(256) void gather_kernel(const float* __restrict__ xin,
                                                     int use_internal) {
    __shared__ __align__(16) char sv[256 * 128];  // 32 KB
    int tid = threadIdx.x;
    int p = blockIdx.x * 256 + tid;
    int k = blockIdx.y;
    int b = blockIdx.z >> 2;
    int cin0 = (blockIdx.z & 3) * 64;
    int h = p >> 6, w = p & 63;

    const float* off = g_offset + ((size_t)b * OC_OFF + 2 * k) * HW + p;
    float dy = off[0];
    float dx = off[HW];
    int ky = k / 3, kx = k - ky * 3;

    float py = dy + (float)(h - 1 + ky);
    float px = dx + (float)(w - 1 + kx);
    float fy = floorf(py), fx = floorf(px);
    int iy0 = (int)fy, ix0 = (int)fx;
    float ly = py - fy, lx = px - fx;

    float vy0 = (iy0 >= 0 && iy0 < H) ? 1.f : 0.f;
    float vy1 = (iy0 + 1 >= 0 && iy0 + 1 < H) ? 1.f : 0.f;
    float vx0 = (ix0 >= 0 && ix0 < W) ? 1.f : 0.f;
    float vx1 = (ix0 + 1 >= 0 && ix0 + 1 < W) ? 1.f : 0.f;

    float w00 = (1.f - ly) * (1.f - lx) * vy0 * vx0;
    float w01 = (1.f - ly) * lx * vy0 * vx1;
    float w10 = ly * (1.f - lx) * vy1 * vx0;
    float w11 = ly * lx * vy1 * vx1;

    int cy0 = min(max(iy0, 0), H - 1);
    int cy1 = min(max(iy0 + 1, 0), H - 1);
    int cx0 = min(max(ix0, 0), W - 1);
    int cx1 = min(max(ix0 + 1, 0), W - 1);
    int i00 = cy0 * W + cx0, i01 = cy0 * W + cx1;
    int i10 = cy1 * W + cx0, i11 = cy1 * W + cx1;

    const float* src = use_internal ? g_act : xin;
    const float* xb = src + (size_t)b * C * HW;

#pragma unroll 1
    for (int g = 0; g < 4; g++) {
        int c0 = cin0 + g * 16;
        const float* xc = xb + (size_t)c0 * HW;
        float v00[16], v01[16], v10[16], v11[16];
#pragma unroll
        for (int j = 0; j < 16; j++) v00[j] = __ldg(xc + (size_t)j * HW + i00);
#pragma unroll
        for (int j = 0; j < 16; j++) v01[j] = __ldg(xc + (size_t)j * HW + i01);
#pragma unroll
        for (int j = 0; j < 16; j++) v10[j] = __ldg(xc + (size_t)j * HW + i10);
#pragma unroll
        for (int j = 0; j < 16; j++) v11[j] = __ldg(xc + (size_t)j * HW + i11);

        __align__(16) __half hb[16];
#pragma unroll
        for (int j = 0; j < 16; j++) {
            float s = w00 * v00[j] + w01 * v01[j] + w10 * v10[j] + w11 * v11[j];
            hb[j] = __float2half(s);
        }
        // swizzled smem write: row tid (128B), cols [g*32, g*32+32) bytes
        uint32_t o0 = (uint32_t)tid * 128 + g * 32;
        uint32_t o1 = o0 + 16;
        *reinterpret_cast<uint4*>(sv + (o0 ^ ((o0 >> 3) & 0x70))) =
            *reinterpret_cast<const uint4*>(hb);
        *reinterpret_cast<uint4*>(sv + (o1 ^ ((o1 >> 3) & 0x70))) =
            *reinterpret_cast<const uint4*>(hb + 8);
    }
    __syncthreads();

    // copy out: 8 threads per pixel -> contiguous 128B per pixel row
    size_t vobase =
        ((size_t)b * HW + (size_t)blockIdx.x * 256) * CK + (size_t)k * 256 + cin0;
#pragma unroll
    for (int t = 0; t < 8; t++) {
        int idx = tid + t * 256;
        int pl = idx >> 3;
        int j = idx & 7;
        uint32_t o = (uint32_t)pl * 128 + j * 16;
        uint4 v = *reinterpret_cast<const uint4*>(sv + (o ^ ((o >> 3) & 0x70)));
        *reinterpret_cast<uint4*>(g_val + vobase + (size_t)pl * CK + j * 8) = v;
    }
}

// ---------------- HMMA GEMM: D[p, oc] = sum_r val[p][r] * W[oc][r] -----------
// CTA tile 128(pixels) x 256(all oc), 512 threads, grid 128 CTAs (one balanced
// wave). fp16 x fp16, fp32 accum. KC=64, 3-stage pipeline, 1 sync per chunk.
#define KC 64
#define NKC (CK / KC) /* 36 */
#define ROWB 144
#define A_OFF 0
#define B_OFF (128 * ROWB)
#define STGSZ (384 * ROWB) /* 55296 */
#define GSMEM (3 * STGSZ)  /* 165888 */

__global__ __launch_bounds__(512, 1) void mma_gemm_kernel(int stage) {
    extern __shared__ __align__(16) char smem[];
    uint32_t sb = smem_u32(smem);
    int tid = threadIdx.x;
    int wid = tid >> 5, lane = tid & 31;
    int b = blockIdx.y;
    int p0 = blockIdx.x * 128;

    const __half* Ag = g_val + ((size_t)b * HW + p0) * CK;
    const __half* Bg = g_wh + (size_t)stage * C * CK;

    // A: 4 thr/row (32B each). B: 2 thr/row (64B each).
    int arow = tid >> 2, aseg = tid & 3;
    size_t agoff = (size_t)arow * CK + aseg * 16;
    uint32_t asoff = (uint32_t)arow * ROWB + (uint32_t)aseg * 32;
    int brow = tid >> 1, bseg = tid & 1;
    size_t bgoff = (size_t)brow * CK + bseg * 32;
    uint32_t bsoff = B_OFF + (uint32_t)brow * ROWB + (uint32_t)bseg * 64;

    int mwarp = wid >> 3, nwarp = wid & 7;
    uint32_t aoff = (uint32_t)(mwarp * 64 + (lane & 15)) * ROWB + (lane >> 4) * 16;
    uint32_t boff = B_OFF +
                    (uint32_t)(nwarp * 32 + (lane >> 4) * 8 + (lane & 7)) * ROWB +
                    ((lane >> 3) & 1) * 16;

    float acc[4][4][4];
#pragma unroll
    for (int i = 0; i < 4; i++)
#pragma unroll
        for (int j = 0; j < 4; j++)
#pragma unroll
            for (int q = 0; q < 4; q++) acc[i][j][q] = 0.f;

    // prologue: stages 0,1
#pragma unroll
    for (int s = 0; s < 2; s++) {
        uint32_t stb = sb + (uint32_t)s * STGSZ;
        int kc = s * KC;
        cp16(stb + A_OFF + asoff, Ag + agoff + kc);
        cp16(stb + A_OFF + asoff + 16, Ag + agoff + kc + 8);
#pragma unroll
        for (int j = 0; j < 4; j++)
            cp16(stb + bsoff + j * 16, Bg + bgoff + kc + j * 8);
        asm volatile("cp.async.commit_group;" ::: "memory");
    }

#pragma unroll 1
    for (int i = 0; i < NKC; i++) {
        asm volatile("cp.async.wait_group 1;" ::: "memory");
        __syncthreads();

        // issue stage i+2 into buffer (i+2)%3 (all warps passed compute i-1)
        if (i + 2 < NKC) {
            uint32_t stb = sb + (uint32_t)((i + 2) % 3) * STGSZ;
            int kc = (i + 2) * KC;
            cp16(stb + A_OFF + asoff, Ag + agoff + kc);
            cp16(stb + A_OFF + asoff + 16, Ag + agoff + kc + 8);
#pragma unroll
            for (int j = 0; j < 4; j++)
                cp16(stb + bsoff + j * 16, Bg + bgoff + kc + j * 8);
        }
        asm volatile("cp.async.commit_group;" ::: "memory");

        uint32_t cb = sb + (uint32_t)(i % 3) * STGSZ;
#pragma unroll
        for (int kk = 0; kk < 4; kk++) {
            uint32_t koff = (uint32_t)kk * 32;
            uint32_t ah[4][4], bb[2][4];
#pragma unroll
            for (int mt = 0; mt < 4; mt++)
                LDSM_X4(ah[mt], cb + A_OFF + aoff + (uint32_t)(mt * 16) * ROWB + koff);
#pragma unroll
            for (int ntp = 0; ntp < 2; ntp++)
                LDSM_X4(bb[ntp], cb + boff + (uint32_t)(ntp * 16) * ROWB + koff);
#pragma unroll
            for (int mt = 0; mt < 4; mt++)
#pragma unroll
                for (int nt = 0; nt < 4; nt++)
                    MMA_F16(acc[mt][nt], ah[mt], &bb[nt >> 1][(nt & 1) * 2]);
        }
    }
    asm volatile("cp.async.wait_group 0;" ::: "memory");
    __syncthreads();

    // ---------------- epilogue: two passes of 128 oc via smem transpose ------
    float* sf = reinterpret_cast<float*>(smem);
    int rl = lane >> 2;
    int cl2 = (lane & 3) * 2;
#pragma unroll 1
    for (int q = 0; q < 2; q++) {
        if ((nwarp >> 2) == q) {
#pragma unroll
            for (int mt = 0; mt < 4; mt++) {
#pragma unroll
                for (int nt = 0; nt < 4; nt++) {
                    int m = mwarp * 64 + mt * 16 + rl;
                    int n = (nwarp & 3) * 32 + nt * 8 + cl2;
                    sf[n * 132 + m] = acc[mt][nt][0];
                    sf[(n + 1) * 132 + m] = acc[mt][nt][1];
                    sf[n * 132 + m + 8] = acc[mt][nt][2];
                    sf[(n + 1) * 132 + m + 8] = acc[mt][nt][3];
                }
            }
        }
        __syncthreads();

#pragma unroll
        for (int t = 0; t < 8; t++) {
            int idx = tid + t * 512;
            int n = idx >> 5;  // constant within a warp
            int ms = (idx & 31) * 4;
            float4 v = *reinterpret_cast<const float4*>(sf + n * 132 + ms);
            int oc = q * 128 + n;
            *reinterpret_cast<float4*>(g_tmp + ((size_t)b * C + oc) * HW + p0 + ms) = v;

            float s1 = v.x + v.y + v.z + v.w;
            float s2 = v.x * v.x + v.y * v.y + v.z * v.z + v.w * v.w;
#pragma unroll
            for (int o = 16; o > 0; o >>= 1) {
                s1 += __shfl_xor_sync(0xffffffffu, s1, o);
                s2 += __shfl_xor_sync(0xffffffffu, s2, o);
            }
            if (lane == 0) {
                int bg = b * G + (oc >> 3);
                atomicAdd(&g_stat[bg * 2], s1);
                atomicAdd(&g_stat[bg * 2 + 1], s2);
            }
        }
        __syncthreads();
    }
}

// ---------------- GroupNorm apply (+ReLU, optional residual) -----------------
// grid (BB*G, 4): each CTA handles 2 of the group's 8 channels.
__global__ __launch_bounds__(256) void gn_kernel(const float* __restrict__ gamma,
                                                 const float* __restrict__ beta,
                                                 const float* __restrict__ residual,
                                                 float* __restrict__ outp,
                                                 int use_internal) {
    int bg = blockIdx.x;
    int b = bg >> 5;
    int g = bg & 31;
    int quarter = blockIdx.y;
    size_t chan_off = ((size_t)b * C + (size_t)g * 8 + (size_t)quarter * 2) * HW;
    const float4* in4 = reinterpret_cast<const float4*>(g_tmp + chan_off);

    __shared__ float stats[2];
    if (threadIdx.x == 0) {
        float inv_n = 1.f / 32768.f;
        float mu = g_stat[bg * 2] * inv_n;
        stats[0] = mu;
        stats[1] = rsqrtf(g_stat[bg * 2 + 1] * inv_n - mu * mu + 1e-5f);
    }
    __syncthreads();
    float mu = stats[0], rstd = stats[1];

    int tid = threadIdx.x;
    float* dst = (use_internal ? g_act : outp) + chan_off;
    float4* out4 = reinterpret_cast<float4*>(dst);
    const float4* res4 =
        residual ? reinterpret_cast<const float4*>(residual + chan_off) : nullptr;

    for (int i = tid; i < 2 * HW / 4; i += 256) {
        int c = g * 8 + quarter * 2 + (i >> 10);
        float gm = gamma[c] * rstd;
        float bt = beta[c] - mu * gm;
        float4 v = in4[i];
        v.x = v.x * gm + bt;
        v.y = v.y * gm + bt;
        v.z = v.z * gm + bt;
        v.w = v.w * gm + bt;
        if (res4) {
            float4 r = res4[i];
            v.x += r.x; v.y += r.y; v.z += r.z; v.w += r.w;
        }
        v.x = fmaxf(v.x, 0.f);
        v.y = fmaxf(v.y, 0.f);
        v.z = fmaxf(v.z, 0.f);
        v.w = fmaxf(v.w, 0.f);
        out4[i] = v;
    }
}

// ---------------- launcher ---------------------------------------------------
extern "C" void kernel_launch(void* const* d_in, const int* in_sizes, int n_in,
                              void* d_out, int out_size) {
    const float* x      = (const float*)d_in[0];
    const float* w_off1 = (const float*)d_in[1];
    const float* b_off1 = (const float*)d_in[2];
    const float* w_off2 = (const float*)d_in[3];
    const float* b_off2 = (const float*)d_in[4];
    const float* w_def1 = (const float*)d_in[5];
    const float* w_def2 = (const float*)d_in[6];
    const float* gamma1 = (const float*)d_in[7];
    const float* beta1  = (const float*)d_in[8];
    const float* gamma2 = (const float*)d_in[9];
    const float* beta2  = (const float*)d_in[10];
    float* out = (float*)d_out;

    cudaFuncSetAttribute(mma_gemm_kernel, cudaFuncAttributeMaxDynamicSharedMemorySize,
                         GSMEM);

    dim3 conv_grid(4, 4, BB * 4);
    dim3 gath_grid(HW / 256, KK, BB * 4);
    dim3 gemm_grid(HW / 128, BB);
    dim3 gn_grid(BB * G, 4);
    int init_blocks = (BB * OC_OFF * HW + 255) / 256;
    int wprep_blocks = (2 * C * CK + 255) / 256;  // covers g_offset init range too

    // ---- stage 1 (stage-1 offset init folded into wprep) ----
    wprep_kernel<<<wprep_blocks, 256>>>(w_def1, w_def2, b_off1);
    offset_conv_kernel<<<conv_grid, 256>>>(x, w_off1, 0);
    gather_kernel<<<gath_grid, 256>>>(x, 0);
    mma_gemm_kernel<<<gemm_grid, 512, GSMEM>>>(0);
    gn_kernel<<<gn_grid, 256>>>(gamma1, beta1, nullptr, nullptr, 1);

    // ---- stage 2 ----
    init_offset_kernel<<<init_blocks, 256>>>(b_off2);
    offset_conv_kernel<<<conv_grid, 256>>>(nullptr, w_off2, 1);
    gather_kernel<<<gath_grid, 256>>>(nullptr, 1);
    mma_gemm_kernel<<<gemm_grid, 512, GSMEM>>>(1);
    gn_kernel<<<gn_grid, 256>>>(gamma2, beta2, x, out, 0);
}

// round 14
// speedup vs baseline: 2.1344x; 1.1374x over previous
#include <cuda_runtime.h>
#include <cuda_fp16.h>
#include <cstdint>

#define BB 4
#define C 256
#define H 64
#define W 64
#define HW 4096
#define G 32
#define KK 9
#define OC_OFF 18
#define CK 2304  /* C * KK */
#define NCHUNK 36 /* CK / 64 */

// ---------------- device scratch (static, no runtime allocation) -------------
__device__ float g_offset[BB * OC_OFF * HW];                        // 1.18 MB
// A blocks: [b][ptile 32][chunk 36] of 16 KB (128 pixels x 128 B, swizzled)
__device__ __align__(16) char g_val2[(size_t)BB * 32 * NCHUNK * 16384];  // 75.5 MB
// B blocks: [stage][chunk 36] of 32 KB (256 oc x 128 B, swizzled)
__device__ __align__(16) char g_wb[2 * NCHUNK * 32768];             // 2.36 MB
__device__ float g_tmp[(size_t)BB * C * HW];                        // 16.8 MB
__device__ float g_act[(size_t)BB * C * HW];                        // 16.8 MB
__device__ float g_stat[BB * G * 2];                                // group sums

// ---------------- helpers ----------------------------------------------------
__device__ __forceinline__ uint32_t smem_u32(const void* p) {
    uint32_t a;
    asm("{ .reg .u64 t; cvta.to.shared.u64 t, %1; cvt.u32.u64 %0, t; }"
        : "=r"(a) : "l"(p));
    return a;
}
__device__ __forceinline__ uint32_t swz(uint32_t o) { return o ^ ((o >> 3) & 0x70); }

__device__ __forceinline__ void bulk_cp(uint32_t sdst, const void* gsrc,
                                        uint32_t bytes, uint32_t mbar) {
    asm volatile(
        "cp.async.bulk.shared::cluster.global.mbarrier::complete_tx::bytes "
        "[%0], [%1], %2, [%3];"
        :: "r"(sdst), "l"(gsrc), "r"(bytes), "r"(mbar) : "memory");
}
__device__ __forceinline__ void mbar_init(uint32_t a, uint32_t cnt) {
    asm volatile("mbarrier.init.shared.b64 [%0], %1;" :: "r"(a), "r"(cnt) : "memory");
}
__device__ __forceinline__ void mbar_expect(uint32_t a, uint32_t bytes) {
    asm volatile("mbarrier.arrive.expect_tx.shared.b64 _, [%0], %1;"
                 :: "r"(a), "r"(bytes) : "memory");
}
__device__ __forceinline__ void mbar_wait(uint32_t a, uint32_t parity) {
    asm volatile(
        "{\n\t.reg .pred P1;\n\t"
        "WL%=:\n\t"
        "mbarrier.try_wait.parity.acquire.cta.shared::cta.b64 P1, [%0], %1, 0x989680;\n\t"
        "@P1 bra.uni WD%=;\n\t"
        "bra.uni WL%=;\n\t"
        "WD%=:\n\t}" :: "r"(a), "r"(parity) : "memory");
}

#define MMA_F16(d, a, bfr)                                                   \
    asm volatile(                                                            \
        "mma.sync.aligned.m16n8k16.row.col.f32.f16.f16.f32 "                 \
        "{%0,%1,%2,%3}, {%4,%5,%6,%7}, {%8,%9}, {%0,%1,%2,%3};"              \
        : "+f"((d)[0]), "+f"((d)[1]), "+f"((d)[2]), "+f"((d)[3])             \
        : "r"((a)[0]), "r"((a)[1]), "r"((a)[2]), "r"((a)[3]),                \
          "r"((bfr)[0]), "r"((bfr)[1]))

#define LDSM_X4(fr, addr)                                                    \
    asm volatile("ldmatrix.sync.aligned.m8n8.x4.shared.b16 "                 \
                 "{%0,%1,%2,%3}, [%4];"                                      \
                 : "=r"((fr)[0]), "=r"((fr)[1]), "=r"((fr)[2]), "=r"((fr)[3])\
                 : "r"(addr))

// ---------------- weight reorder (swizzled chunk blocks) + stage-1 init ------
__global__ void wprep_kernel(const float* __restrict__ w1, const float* __restrict__ w2,
                             const float* __restrict__ bias1) {
    int i = blockIdx.x * 256 + threadIdx.x;
    if (blockIdx.x == 0 && threadIdx.x < BB * G * 2) g_stat[threadIdx.x] = 0.f;
    if (i < BB * OC_OFF * HW) {
        int oc = (i / HW) % OC_OFF;
        g_offset[i] = bias1[oc];
    }
    if (i >= 2 * C * CK) return;
    int s = i / (C * CK);
    int rem = i - s * (C * CK);
    int oc = rem / CK;
    int r = rem - oc * CK;
    int k = r >> 8;
    int cin = r & 255;
    const float* w = s ? w2 : w1;
    __half hv = __float2half(w[(size_t)oc * CK + cin * 9 + k]);
    // B block layout: chunk = r/64, row oc (128B), col (r%64)*2, swizzled
    int chunk = r >> 6;
    uint32_t o = (uint32_t)oc * 128 + (uint32_t)(r & 63) * 2;
    *reinterpret_cast<unsigned short*>(
        g_wb + (((size_t)s * NCHUNK + chunk) << 15) + swz(o)) =
        __half_as_ushort(hv);
}

// ---------------- init offset buffer with bias + clear group stats -----------
__global__ void init_offset_kernel(const float* __restrict__ bias) {
    int i = blockIdx.x * 256 + threadIdx.x;
    if (blockIdx.x == 0 && threadIdx.x < BB * G * 2) g_stat[threadIdx.x] = 0.f;
    if (i < BB * OC_OFF * HW) {
        int oc = (i / HW) % OC_OFF;
        g_offset[i] = bias[oc];
    }
}

// ---------------- offset conv3x3: C in -> 18 out, pad 1 ----------------------
#define CIN_CHUNK 64
__global__ __launch_bounds__(256) void offset_conv_kernel(
    const float* __restrict__ xin, const float* __restrict__ woff, int use_internal) {
    __shared__ __align__(16) float ws[CIN_CHUNK * 9 * 20];
    __shared__ float xs[2][18 * 18];

    int tid = threadIdx.x;
    int bz = blockIdx.z;
    int b = bz >> 2;
    int chunk = bz & 3;
    int cin0 = chunk * CIN_CHUNK;

    for (int idx = tid; idx < CIN_CHUNK * 9 * 18; idx += 256) {
        int cl = idx / 162;
        int rem = idx - cl * 162;
        int k = rem / 18;
        int oc = rem - k * 18;
        ws[(cl * 9 + k) * 20 + oc] =
            woff[(size_t)oc * (C * 9) + (size_t)(cin0 + cl) * 9 + k];
    }

    int ty = tid >> 4, tx = tid & 15;
    int py0 = blockIdx.y * 16, px0 = blockIdx.x * 16;

    float acc[18];
#pragma unroll
    for (int i = 0; i < 18; i++) acc[i] = 0.f;

    const float* src = use_internal ? g_act : xin;
    const float* xb = src + ((size_t)b * C + cin0) * HW;

    int hidx0 = tid;
    int hidx1 = tid + 256;
    int hr0 = hidx0 / 18, hc0 = hidx0 - hr0 * 18;
    int hr1 = hidx1 / 18, hc1 = hidx1 - hr1 * 18;
    int gy0 = py0 - 1 + hr0, gx0 = px0 - 1 + hc0;
    int gy1 = py0 - 1 + hr1, gx1 = px0 - 1 + hc1;
    bool v0 = (gy0 >= 0 && gy0 < H && gx0 >= 0 && gx0 < W);
    bool v1 = (hidx1 < 324) && (gy1 >= 0 && gy1 < H && gx1 >= 0 && gx1 < W);
    int go0 = gy0 * W + gx0, go1 = gy1 * W + gx1;

    {
        const float* xc = xb;
        xs[0][hidx0] = v0 ? xc[go0] : 0.f;
        if (hidx1 < 324) xs[0][hidx1] = v1 ? xc[go1] : 0.f;
    }
    __syncthreads();

#pragma unroll 1
    for (int cl = 0; cl < CIN_CHUNK; cl++) {
        int cur = cl & 1;
        if (cl + 1 < CIN_CHUNK) {
            const float* xn = xb + (size_t)(cl + 1) * HW;
            xs[cur ^ 1][hidx0] = v0 ? __ldg(xn + go0) : 0.f;
            if (hidx1 < 324) xs[cur ^ 1][hidx1] = v1 ? __ldg(xn + go1) : 0.f;
        }

        float xv[9];
#pragma unroll
        for (int ky = 0; ky < 3; ky++)
#pragma unroll
            for (int kx = 0; kx < 3; kx++)
                xv[ky * 3 + kx] = xs[cur][(ty + ky) * 18 + (tx + kx)];

#pragma unroll
        for (int k = 0; k < 9; k++) {
            const float* wr = &ws[(cl * 9 + k) * 20];
            float xk = xv[k];
#pragma unroll
            for (int oc = 0; oc < 18; oc++) acc[oc] += xk * wr[oc];
        }
        __syncthreads();
    }

    int p = (py0 + ty) * W + (px0 + tx);
    float* ob = g_offset + (size_t)b * OC_OFF * HW + p;
#pragma unroll
    for (int oc = 0; oc < 18; oc++) atomicAdd(ob + (size_t)oc * HW, acc[oc]);
}

// ---------------- bilinear gather -> swizzled A blocks (fp16) ----------------
// grid (16, 9, B*4). Compute into swizzled smem, then LINEAR copy-out into
// g_val2 chunk blocks (smem image == gmem image, both swizzled).
__global__ __launch_bounds__(256) void gather_kernel(const float* __restrict__ xin,
                                                     int use_internal) {
    __shared__ __align__(16) char sv[256 * 128];  // 32 KB = 2 ptile blocks
    int tid = threadIdx.x;
    int p = blockIdx.x * 256 + tid;
    int k = blockIdx.y;
    int b = blockIdx.z >> 2;
    int cin0 = (blockIdx.z & 3) * 64;
    int h = p >> 6, w = p & 63;

    const float* off = g_offset + ((size_t)b * OC_OFF + 2 * k) * HW + p;
    float dy = off[0];
    float dx = off[HW];
    int ky = k / 3, kx = k - ky * 3;

    float py = dy + (float)(h - 1 + ky);
    float px = dx + (float)(w - 1 + kx);
    float fy = floorf(py), fx = floorf(px);
    int iy0 = (int)fy, ix0 = (int)fx;
    float ly = py - fy, lx = px - fx;

    float vy0 = (iy0 >= 0 && iy0 < H) ? 1.f : 0.f;
    float vy1 = (iy0 + 1 >= 0 && iy0 + 1 < H) ? 1.f : 0.f;
    float vx0 = (ix0 >= 0 && ix0 < W) ? 1.f : 0.f;
    float vx1 = (ix0 + 1 >= 0 && ix0 + 1 < W) ? 1.f : 0.f;

    float w00 = (1.f - ly) * (1.f - lx) * vy0 * vx0;
    float w01 = (1.f - ly) * lx * vy0 * vx1;
    float w10 = ly * (1.f - lx) * vy1 * vx0;
    float w11 = ly * lx * vy1 * vx1;

    int cy0 = min(max(iy0, 0), H - 1);
    int cy1 = min(max(iy0 + 1, 0), H - 1);
    int cx0 = min(max(ix0, 0), W - 1);
    int cx1 = min(max(ix0 + 1, 0), W - 1);
    int i00 = cy0 * W + cx0, i01 = cy0 * W + cx1;
    int i10 = cy1 * W + cx0, i11 = cy1 * W + cx1;

    const float* src = use_internal ? g_act : xin;
    const float* xb = src + (size_t)b * C * HW;

#pragma unroll 1
    for (int g = 0; g < 4; g++) {
        int c0 = cin0 + g * 16;
        const float* xc = xb + (size_t)c0 * HW;
        float v00[16], v01[16], v10[16], v11[16];
#pragma unroll
        for (int j = 0; j < 16; j++) v00[j] = __ldg(xc + (size_t)j * HW + i00);
#pragma unroll
        for (int j = 0; j < 16; j++) v01[j] = __ldg(xc + (size_t)j * HW + i01);
#pragma unroll
        for (int j = 0; j < 16; j++) v10[j] = __ldg(xc + (size_t)j * HW + i10);
#pragma unroll
        for (int j = 0; j < 16; j++) v11[j] = __ldg(xc + (size_t)j * HW + i11);

        __align__(16) __half hb[16];
#pragma unroll
        for (int j = 0; j < 16; j++) {
            float s = w00 * v00[j] + w01 * v01[j] + w10 * v10[j] + w11 * v11[j];
            hb[j] = __float2half(s);
        }
        uint32_t o0 = (uint32_t)tid * 128 + g * 32;
        uint32_t o1 = o0 + 16;
        *reinterpret_cast<uint4*>(sv + swz(o0)) = *reinterpret_cast<const uint4*>(hb);
        *reinterpret_cast<uint4*>(sv + swz(o1)) =
            *reinterpret_cast<const uint4*>(hb + 8);
    }
    __syncthreads();

    // linear copy-out: smem already holds the swizzled block image
    int chunk = k * 4 + (blockIdx.z & 3);
#pragma unroll
    for (int t = 0; t < 8; t++) {
        uint32_t idx = ((uint32_t)tid + t * 256) * 16;
        int pt = blockIdx.x * 2 + (idx >> 14);
        size_t base = (((size_t)b * 32 + pt) * NCHUNK + chunk) << 14;
        *reinterpret_cast<uint4*>(g_val2 + base + (idx & 16383)) =
            *reinterpret_cast<const uint4*>(sv + idx);
    }
}

// ---------------- HMMA GEMM with cp.async.bulk chunk loads -------------------
// CTA tile 128(pixels) x 256(oc), 512 threads, grid (32, BB). fp16 x fp16,
// fp32 accum. 3-stage mbarrier pipeline; A 16KB + B 32KB bulk per chunk.
// Swizzle applied to the FULL offset (row + col + koff) at each ldmatrix.
#define STG 49152
#define GSMEM (3 * STG) /* 147456 */

__global__ __launch_bounds__(512, 1) void mma_gemm_kernel(int stage) {
    extern __shared__ __align__(16) char smem[];
    __shared__ __align__(8) unsigned long long mb8[3];
    uint32_t sb = smem_u32(smem);
    uint32_t mb = smem_u32(mb8);
    int tid = threadIdx.x;
    int wid = tid >> 5, lane = tid & 31;
    int b = blockIdx.y;
    int ptile = blockIdx.x;
    int p0 = ptile * 128;

    const char* Ag = g_val2 + (((size_t)b * 32 + ptile) * NCHUNK << 14);
    const char* Bg = g_wb + ((size_t)stage * NCHUNK << 15);

    if (tid == 0) {
#pragma unroll
        for (int s = 0; s < 3; s++) mbar_init(mb + 8 * s, 1);
    }
    __syncthreads();

    // prologue: fill stages 0..2
    if (tid == 0) {
#pragma unroll
        for (int s = 0; s < 3; s++) {
            mbar_expect(mb + 8 * s, 49152);
            bulk_cp(sb + s * STG, Ag + ((size_t)s << 14), 16384, mb + 8 * s);
            bulk_cp(sb + s * STG + 16384, Bg + ((size_t)s << 15), 32768, mb + 8 * s);
        }
    }

    int mwarp = wid >> 3, nwarp = wid & 7;
    // unswizzled components; swizzle applied per-access on the full offset
    uint32_t arow_off[4];
#pragma unroll
    for (int mt = 0; mt < 4; mt++)
        arow_off[mt] = (uint32_t)(mwarp * 64 + mt * 16 + (lane & 15)) * 128;
    uint32_t acol = (lane >> 4) * 16;
    uint32_t brow_off[2];
#pragma unroll
    for (int ntp = 0; ntp < 2; ntp++)
        brow_off[ntp] =
            (uint32_t)(nwarp * 32 + ntp * 16 + (lane >> 4) * 8 + (lane & 7)) * 128;
    uint32_t bcol = ((lane >> 3) & 1) * 16;

    float acc[4][4][4];
#pragma unroll
    for (int i = 0; i < 4; i++)
#pragma unroll
        for (int j = 0; j < 4; j++)
#pragma unroll
            for (int q = 0; q < 4; q++) acc[i][j][q] = 0.f;

#pragma unroll 1
    for (int i = 0; i < NCHUNK; i++) {
        int buf = i % 3;
        mbar_wait(mb + 8 * buf, (i / 3) & 1);

        uint32_t cb = sb + (uint32_t)buf * STG;
#pragma unroll
        for (int kk = 0; kk < 4; kk++) {
            uint32_t koff = (uint32_t)kk * 32;
            uint32_t ah[4][4], bb[2][4];
#pragma unroll
            for (int mt = 0; mt < 4; mt++)
                LDSM_X4(ah[mt], cb + swz(arow_off[mt] + acol + koff));
#pragma unroll
            for (int ntp = 0; ntp < 2; ntp++)
                LDSM_X4(bb[ntp], cb + 16384 + swz(brow_off[ntp] + bcol + koff));
#pragma unroll
            for (int mt = 0; mt < 4; mt++)
#pragma unroll
                for (int nt = 0; nt < 4; nt++)
                    MMA_F16(acc[mt][nt], ah[mt], &bb[nt >> 1][(nt & 1) * 2]);
        }
        __syncthreads();

        if (tid == 0 && i + 3 < NCHUNK) {
            int nc = i + 3;
            mbar_expect(mb + 8 * buf, 49152);
            bulk_cp(cb, Ag + ((size_t)nc << 14), 16384, mb + 8 * buf);
            bulk_cp(cb + 16384, Bg + ((size_t)nc << 15), 32768, mb + 8 * buf);
        }
    }

    // ---------------- epilogue: two passes of 128 oc via smem transpose ------
    float* sf = reinterpret_cast<float*>(smem);
    int rl = lane >> 2;
    int cl2 = (lane & 3) * 2;
#pragma unroll 1
    for (int q = 0; q < 2; q++) {
        if ((nwarp >> 2) == q) {
#pragma unroll
            for (int mt = 0; mt < 4; mt++) {
#pragma unroll
                for (int nt = 0; nt < 4; nt++) {
                    int m = mwarp * 64 + mt * 16 + rl;
                    int n = (nwarp & 3) * 32 + nt * 8 + cl2;
                    sf[n * 132 + m] = acc[mt][nt][0];
                    sf[(n + 1) * 132 + m] = acc[mt][nt][1];
                    sf[n * 132 + m + 8] = acc[mt][nt][2];
                    sf[(n + 1) * 132 + m + 8] = acc[mt][nt][3];
                }
            }
        }
        __syncthreads();

#pragma unroll
        for (int t = 0; t < 8; t++) {
            int idx = tid + t * 512;
            int n = idx >> 5;
            int ms = (idx & 31) * 4;
            float4 v = *reinterpret_cast<const float4*>(sf + n * 132 + ms);
            int oc = q * 128 + n;
            *reinterpret_cast<float4*>(g_tmp + ((size_t)b * C + oc) * HW + p0 + ms) = v;

            float s1 = v.x + v.y + v.z + v.w;
            float s2 = v.x * v.x + v.y * v.y + v.z * v.z + v.w * v.w;
#pragma unroll
            for (int o = 16; o > 0; o >>= 1) {
                s1 += __shfl_xor_sync(0xffffffffu, s1, o);
                s2 += __shfl_xor_sync(0xffffffffu, s2, o);
            }
            if (lane == 0) {
                int bg = b * G + (oc >> 3);
                atomicAdd(&g_stat[bg * 2], s1);
                atomicAdd(&g_stat[bg * 2 + 1], s2);
            }
        }
        __syncthreads();
    }
}

// ---------------- GroupNorm apply (+ReLU, optional residual) -----------------
__global__ __launch_bounds__(256) void gn_kernel(const float* __restrict__ gamma,
                                                 const float* __restrict__ beta,
                                                 const float* __restrict__ residual,
                                                 float* __restrict__ outp,
                                                 int use_internal) {
    int bg = blockIdx.x;
    int b = bg >> 5;
    int g = bg & 31;
    int quarter = blockIdx.y;
    size_t chan_off = ((size_t)b * C + (size_t)g * 8 + (size_t)quarter * 2) * HW;
    const float4* in4 = reinterpret_cast<const float4*>(g_tmp + chan_off);

    __shared__ float stats[2];
    if (threadIdx.x == 0) {
        float inv_n = 1.f / 32768.f;
        float mu = g_stat[bg * 2] * inv_n;
        stats[0] = mu;
        stats[1] = rsqrtf(g_stat[bg * 2 + 1] * inv_n - mu * mu + 1e-5f);
    }
    __syncthreads();
    float mu = stats[0], rstd = stats[1];

    int tid = threadIdx.x;
    float* dst = (use_internal ? g_act : outp) + chan_off;
    float4* out4 = reinterpret_cast<float4*>(dst);
    const float4* res4 =
        residual ? reinterpret_cast<const float4*>(residual + chan_off) : nullptr;

    for (int i = tid; i < 2 * HW / 4; i += 256) {
        int c = g * 8 + quarter * 2 + (i >> 10);
        float gm = gamma[c] * rstd;
        float bt = beta[c] - mu * gm;
        float4 v = in4[i];
        v.x = v.x * gm + bt;
        v.y = v.y * gm + bt;
        v.z = v.z * gm + bt;
        v.w = v.w * gm + bt;
        if (res4) {
            float4 r = res4[i];
            v.x += r.x; v.y += r.y; v.z += r.z; v.w += r.w;
        }
        v.x = fmaxf(v.x, 0.f);
        v.y = fmaxf(v.y, 0.f);
        v.z = fmaxf(v.z, 0.f);
        v.w = fmaxf(v.w, 0.f);
        out4[i] = v;
    }
}

// ---------------- launcher ---------------------------------------------------
extern "C" void kernel_launch(void* const* d_in, const int* in_sizes, int n_in,
                              void* d_out, int out_size) {
    const float* x      = (const float*)d_in[0];
    const float* w_off1 = (const float*)d_in[1];
    const float* b_off1 = (const float*)d_in[2];
    const float* w_off2 = (const float*)d_in[3];
    const float* b_off2 = (const float*)d_in[4];
    const float* w_def1 = (const float*)d_in[5];
    const float* w_def2 = (const float*)d_in[6];
    const float* gamma1 = (const float*)d_in[7];
    const float* beta1  = (const float*)d_in[8];
    const float* gamma2 = (const float*)d_in[9];
    const float* beta2  = (const float*)d_in[10];
    float* out = (float*)d_out;

    cudaFuncSetAttribute(mma_gemm_kernel, cudaFuncAttributeMaxDynamicSharedMemorySize,
                         GSMEM);

    dim3 conv_grid(4, 4, BB * 4);
    dim3 gath_grid(HW / 256, KK, BB * 4);
    dim3 gemm_grid(HW / 128, BB);
    dim3 gn_grid(BB * G, 4);
    int init_blocks = (BB * OC_OFF * HW + 255) / 256;
    int wprep_blocks = (2 * C * CK + 255) / 256;  // covers g_offset init range too

    // ---- stage 1 (stage-1 offset init folded into wprep) ----
    wprep_kernel<<<wprep_blocks, 256>>>(w_def1, w_def2, b_off1);
    offset_conv_kernel<<<conv_grid, 256>>>(x, w_off1, 0);
    gather_kernel<<<gath_grid, 256>>>(x, 0);
    mma_gemm_kernel<<<gemm_grid, 512, GSMEM>>>(0);
    gn_kernel<<<gn_grid, 256>>>(gamma1, beta1, nullptr, nullptr, 1);

    // ---- stage 2 ----
    init_offset_kernel<<<init_blocks, 256>>>(b_off2);
    offset_conv_kernel<<<conv_grid, 256>>>(nullptr, w_off2, 1);
    gather_kernel<<<gath_grid, 256>>>(nullptr, 1);
    mma_gemm_kernel<<<gemm_grid, 512, GSMEM>>>(1);
    gn_kernel<<<gn_grid, 256>>>(gamma2, beta2, x, out, 0);
}